// round 4
// baseline (speedup 1.0000x reference)
#include <cuda_runtime.h>

#define NN 50000
#define NE 800000
#define NB 64

typedef unsigned long long ull;

// ---------------- scratch (device globals: allocation-free) ----------------
__device__ __align__(16) float g_node[NN * 32];
__device__ __align__(16) float g_P[NN * 32];
__device__ __align__(16) float g_Q[NN * 32];
__device__ __align__(16) float g_pvc[NN * 32];
__device__ int   g_cnt[NN];
__device__ int   g_off[NN + 1];
__device__ int   g_cur[NN];
__device__ int   g_csr[2 * NE];
__device__ int   g_bsum[NB];
__device__ int   g_bpre[NB];

// ---------------- f32x2 packed helpers ----------------
__device__ __forceinline__ ull pk2(float x, float y) {
    ull r;
    asm("mov.b64 %0, {%1, %2};" : "=l"(r) : "f"(x), "f"(y));
    return r;
}
__device__ __forceinline__ void unpk2(float& x, float& y, ull v) {
    asm("mov.b64 {%0, %1}, %2;" : "=f"(x), "=f"(y) : "l"(v));
}
__device__ __forceinline__ void ffma2(ull& d, ull a, ull b) {
    asm("fma.rn.f32x2 %0, %1, %2, %3;" : "=l"(d) : "l"(a), "l"(b), "l"(d));
}
__device__ __forceinline__ ull add2(ull a, ull b) {
    ull r;
    asm("add.rn.f32x2 %0, %1, %2;" : "=l"(r) : "l"(a), "l"(b));
    return r;
}

// ---------------- prep kernels ----------------
__global__ void zero_cnt_kernel(int n) {
    int i = blockIdx.x * blockDim.x + threadIdx.x;
    if (i < n) g_cnt[i] = 0;
}

__global__ void embed_pvc_kernel(const float* __restrict__ classes,
                                 const float* __restrict__ pos,
                                 const float* __restrict__ Win,
                                 const float* __restrict__ bin,
                                 const float* __restrict__ W1,
                                 int n_nodes) {
    int warp = (blockIdx.x * blockDim.x + threadIdx.x) >> 5;
    int j = threadIdx.x & 31;
    if (warp >= n_nodes) return;
    int u = warp;

    float w[16];
#pragma unroll
    for (int k = 0; k < 16; k++) w[k] = Win[j * 16 + k];
    float c = (j < 16) ? classes[u * 16 + j] : 0.f;
    float acc = bin[j];
#pragma unroll
    for (int k = 0; k < 16; k++)
        acc = fmaf(w[k], __shfl_sync(0xffffffffu, c, k), acc);
    g_node[u * 32 + j] = acc;

    float p0 = pos[u * 3 + 0], p1 = pos[u * 3 + 1], p2 = pos[u * 3 + 2];
    float pv = p0 * W1[j * 67 + 64] + p1 * W1[j * 67 + 65] + p2 * W1[j * 67 + 66];
    g_pvc[u * 32 + j] = pv;
}

__global__ void count_kernel(const int* __restrict__ e, int n2e) {
    int i = blockIdx.x * blockDim.x + threadIdx.x;
    if (i < n2e) atomicAdd(&g_cnt[e[i]], 1);
}

__global__ void scan1_kernel(int n, int seg) {
    int b = blockIdx.x;
    int beg = b * seg, end = min(beg + seg, n);
    int tid = threadIdx.x;
    int s = 0;
    for (int i = beg + tid; i < end; i += 256) s += g_cnt[i];
    __shared__ int sm[8];
    int lane = tid & 31, w = tid >> 5;
#pragma unroll
    for (int o = 16; o >= 1; o >>= 1) s += __shfl_down_sync(0xffffffffu, s, o);
    if (lane == 0) sm[w] = s;
    __syncthreads();
    if (tid == 0) {
        int t = 0;
#pragma unroll
        for (int k = 0; k < 8; k++) t += sm[k];
        g_bsum[b] = t;
    }
}

__global__ void scan2_kernel() {
    int tid = threadIdx.x;
    int s = g_bsum[tid];
    int lane = tid & 31, w = tid >> 5;
    int v = s;
#pragma unroll
    for (int o = 1; o < 32; o <<= 1) {
        int t = __shfl_up_sync(0xffffffffu, v, o);
        if (lane >= o) v += t;
    }
    __shared__ int w0tot;
    if (tid == 31) w0tot = v;
    __syncthreads();
    int incl = v + (w == 1 ? w0tot : 0);
    g_bpre[tid] = incl - s;
}

__global__ void scan3_kernel(int n, int seg) {
    int b = blockIdx.x, tid = threadIdx.x;
    int beg = b * seg, end = min(beg + seg, n);
    int len = max(end - beg, 0);
    int c = (len + 255) / 256;
    int tb = min(beg + tid * c, end), te = min(tb + c, end);
    int s = 0;
    for (int i = tb; i < te; i++) s += g_cnt[i];
    int lane = tid & 31, w = tid >> 5;
    int v = s;
#pragma unroll
    for (int o = 1; o < 32; o <<= 1) {
        int t = __shfl_up_sync(0xffffffffu, v, o);
        if (lane >= o) v += t;
    }
    __shared__ int wt[8], wpre[8];
    if (lane == 31) wt[w] = v;
    __syncthreads();
    if (tid < 8) {
        int x = wt[tid];
#pragma unroll
        for (int o = 1; o < 8; o <<= 1) {
            int t = __shfl_up_sync(0xffu, x, o);
            if (tid >= o) x += t;
        }
        wpre[tid] = x;
    }
    __syncthreads();
    int excl = (v - s) + (w > 0 ? wpre[w - 1] : 0);
    int run = g_bpre[b] + excl;
    for (int i = tb; i < te; i++) {
        g_off[i] = run;
        g_cur[i] = run;
        run += g_cnt[i];
    }
    if (b == gridDim.x - 1 && tid == 255) g_off[n] = run;
}

__global__ void scatter_kernel(const int* __restrict__ e, int nE) {
    int i = blockIdx.x * blockDim.x + threadIdx.x;
    if (i >= 2 * nE) return;
    int src = e[i];
    int dst = (i < nE) ? e[i + nE] : e[i - nE];
    int slot = atomicAdd(&g_cur[src], 1);
    g_csr[slot] = dst;
}

// ---------------- per-iteration kernels ----------------
__global__ void __launch_bounds__(256) pq_kernel(const float* __restrict__ W1,
                                                 const float* __restrict__ b1,
                                                 int n_nodes) {
    int j = threadIdx.x & 31;
    int wl = threadIdx.x >> 5;
    float wa[32], wb[32];
#pragma unroll
    for (int k = 0; k < 32; k++) {
        wa[k] = W1[j * 67 + k];
        wb[k] = W1[j * 67 + 32 + k];
    }
    float bj = b1[j];
    int nw = gridDim.x * 8;
    for (int u = blockIdx.x * 8 + wl; u < n_nodes; u += nw) {
        float nd = g_node[u * 32 + j];
        float p = 0.f, q = 0.f;
#pragma unroll
        for (int k = 0; k < 32; k++) {
            float v = __shfl_sync(0xffffffffu, nd, k);
            p = fmaf(wa[k], v, p);
            q = fmaf(wb[k], v, q);
        }
        float pv = g_pvc[u * 32 + j];
        g_P[u * 32 + j] = p + bj - pv;
        g_Q[u * 32 + j] = q + pv;
    }
}

// Fused hot kernel: persistent warp per node-stream, software-pipelined.
//   prefetch: next chunk's CSR ids + 8x LDG.128 Q rows into registers
//   store:    relu(P[u]+Q[v]) tile -> smem (STS.128)
//   pass2:    ulonglong2 LDS.128 rows x packed W2 regs, fma.rn.f32x2 (FFMA2)
//   epilogue: a = acc@W3.T + deg*b3 (packed, smem-staged), then GRU.
__global__ void __launch_bounds__(128) edge_gru_kernel(
        const float* __restrict__ W2, const float* __restrict__ b2,
        const float* __restrict__ W3, const float* __restrict__ b3,
        const float* __restrict__ Wih, const float* __restrict__ Whh,
        const float* __restrict__ bih, const float* __restrict__ bhh,
        float* __restrict__ out, int n_nodes) {
    __shared__ float A_s[4][32][32];     // 16KB per-warp h1 tile
    __shared__ float2 sWi2[32][32];      // 8KB (r,z) of Wih^T
    __shared__ float  sWin[32][32];      // 4KB n of Wih^T
    __shared__ float2 sWh2[32][32];      // 8KB
    __shared__ float  sWhn[32][32];      // 4KB
    __shared__ ull    sW3p[16][32];      // 4KB W3 row-pairs packed
    int tid = threadIdx.x, wl = tid >> 5, j = tid & 31;

    for (int idx = tid; idx < 1024; idx += 128) {
        int k = idx >> 5, jj = idx & 31;
        sWi2[k][jj] = make_float2(Wih[jj * 32 + k], Wih[(jj + 32) * 32 + k]);
        sWin[k][jj] = Wih[(jj + 64) * 32 + k];
        sWh2[k][jj] = make_float2(Whh[jj * 32 + k], Whh[(jj + 32) * 32 + k]);
        sWhn[k][jj] = Whh[(jj + 64) * 32 + k];
        if (k < 16) sW3p[k][jj] = pk2(W3[jj * 32 + 2 * k], W3[jj * 32 + 2 * k + 1]);
    }
    __syncthreads();

    ull w2p[16];
#pragma unroll
    for (int i = 0; i < 16; i++)
        w2p[i] = pk2(W2[j * 32 + 2 * i], W2[j * 32 + 2 * i + 1]);
    float bb2 = b2[j], bb3 = b3[j];
    float br = bih[j], bz = bih[j + 32], bn = bih[j + 64];
    float cr = bhh[j], cz = bhh[j + 32], cn = bhh[j + 64];

    float (*A)[32] = A_s[wl];
    int sub = j >> 3;     // row subgroup 0..3
    int qcol = j & 7;     // float4 column
    int nw = gridDim.x * 4;

    for (int u = blockIdx.x * 4 + wl; u < n_nodes; u += nw) {
        float pj = g_P[(size_t)u * 32 + j];
        float4 pq4;
        pq4.x = __shfl_sync(0xffffffffu, pj, qcol * 4 + 0);
        pq4.y = __shfl_sync(0xffffffffu, pj, qcol * 4 + 1);
        pq4.z = __shfl_sync(0xffffffffu, pj, qcol * 4 + 2);
        pq4.w = __shfl_sync(0xffffffffu, pj, qcol * 4 + 3);

        int s = g_off[u], e = g_off[u + 1];
        float acc = 0.f;
        float4 q[8];

        // prologue: prefetch first chunk
        if (s < e) {
            int idx0 = s + j;
            int v = (idx0 < e) ? g_csr[idx0] : 0;
#pragma unroll
            for (int it = 0; it < 8; it++) {
                int vv = __shfl_sync(0xffffffffu, v, it * 4 + sub);
                q[it] = *(const float4*)&g_Q[(size_t)vv * 32 + qcol * 4];
            }
        }

        for (int base = s; base < e; base += 32) {
            int cnt = min(32, e - base);
            __syncwarp();   // prior pass2 reads done before overwrite
#pragma unroll
            for (int it = 0; it < 8; it++) {
                float4 hh;
                hh.x = fmaxf(pq4.x + q[it].x, 0.f);
                hh.y = fmaxf(pq4.y + q[it].y, 0.f);
                hh.z = fmaxf(pq4.z + q[it].z, 0.f);
                hh.w = fmaxf(pq4.w + q[it].w, 0.f);
                *(float4*)&A[it * 4 + sub][qcol * 4] = hh;
            }
            __syncwarp();

            // prefetch next chunk while pass2 runs (loads overlap compute)
            int nbase = base + 32;
            if (nbase < e) {
                int idxn = nbase + j;
                int v = (idxn < e) ? g_csr[idxn] : 0;
#pragma unroll
                for (int it = 0; it < 8; it++) {
                    int vv = __shfl_sync(0xffffffffu, v, it * 4 + sub);
                    q[it] = *(const float4*)&g_Q[(size_t)vv * 32 + qcol * 4];
                }
            }

            // pass2: packed-f32x2 GEMM rows
#pragma unroll 4
            for (int t = 0; t < cnt; t++) {
                const ulonglong2* row = (const ulonglong2*)A[t];
                ull a0 = pk2(bb2, 0.f), a1 = 0ull;
#pragma unroll
                for (int c = 0; c < 8; c++) {
                    ulonglong2 r = row[c];
                    ffma2(a0, w2p[2 * c + 0], r.x);
                    ffma2(a1, w2p[2 * c + 1], r.y);
                }
                ull ssum = add2(a0, a1);
                float lo, hi;
                unpk2(lo, hi, ssum);
                acc += fmaxf(lo + hi, 0.f);
            }
        }

        // layer-3 epilogue (commutes with segment-sum), packed via smem staging
        __syncwarp();
        A[0][j] = acc;
        __syncwarp();
        {
            const ull* ar = (const ull*)A[0];
            ull ap = pk2((float)(e - s) * bb3, 0.f);
#pragma unroll
            for (int c = 0; c < 16; c++)
                ffma2(ap, sW3p[c][j], ar[c]);
            float lo, hi;
            unpk2(lo, hi, ap);
            float a = lo + hi;

            // GRU (torch gate order r,z,n)
            float h = g_node[(size_t)u * 32 + j];
            float gir = br, giz = bz, gin = bn, ghr = cr, ghz = cz, ghn = cn;
#pragma unroll
            for (int k = 0; k < 32; k++) {
                float xa = __shfl_sync(0xffffffffu, a, k);
                float hb = __shfl_sync(0xffffffffu, h, k);
                float2 wi = sWi2[k][j];
                float win = sWin[k][j];
                float2 wh = sWh2[k][j];
                float whn = sWhn[k][j];
                gir = fmaf(wi.x, xa, gir); giz = fmaf(wi.y, xa, giz); gin = fmaf(win, xa, gin);
                ghr = fmaf(wh.x, hb, ghr); ghz = fmaf(wh.y, hb, ghz); ghn = fmaf(whn, hb, ghn);
            }
            float r = 1.f / (1.f + expf(-(gir + ghr)));
            float z = 1.f / (1.f + expf(-(giz + ghz)));
            float nv = tanhf(gin + r * ghn);
            float nh = (1.f - z) * nv + z * h;
            g_node[(size_t)u * 32 + j] = nh;
            if (out) out[(size_t)u * 32 + j] = nh;
        }
    }
}

// ---------------- launch ----------------
extern "C" void kernel_launch(void* const* d_in, const int* in_sizes, int n_in,
                              void* d_out, int out_size) {
    const float* pos     = (const float*)d_in[0];
    const float* classes = (const float*)d_in[1];
    const int*   edges   = (const int*)d_in[2];
    int wb = (in_sizes[3] == 1) ? 4 : 3;
    const float* Win = (const float*)d_in[wb + 0];
    const float* bin = (const float*)d_in[wb + 1];
    const float* W1  = (const float*)d_in[wb + 2];
    const float* b1  = (const float*)d_in[wb + 3];
    const float* W2  = (const float*)d_in[wb + 4];
    const float* b2  = (const float*)d_in[wb + 5];
    const float* W3  = (const float*)d_in[wb + 6];
    const float* b3  = (const float*)d_in[wb + 7];
    const float* Wih = (const float*)d_in[wb + 8];
    const float* Whh = (const float*)d_in[wb + 9];
    const float* bih = (const float*)d_in[wb + 10];
    const float* bhh = (const float*)d_in[wb + 11];

    int n_nodes = in_sizes[0] / 3;
    int n_edges = in_sizes[2] / 2;
    int n2e = 2 * n_edges;
    float* out = (float*)d_out;
    int seg = (n_nodes + NB - 1) / NB;

    zero_cnt_kernel<<<(n_nodes + 255) / 256, 256>>>(n_nodes);
    embed_pvc_kernel<<<(n_nodes + 7) / 8, 256>>>(classes, pos, Win, bin, W1, n_nodes);
    count_kernel<<<(n2e + 255) / 256, 256>>>(edges, n2e);
    scan1_kernel<<<NB, 256>>>(n_nodes, seg);
    scan2_kernel<<<1, 64>>>();
    scan3_kernel<<<NB, 256>>>(n_nodes, seg);
    scatter_kernel<<<(n2e + 255) / 256, 256>>>(edges, n_edges);

    for (int it = 0; it < 6; ++it) {
        pq_kernel<<<296, 256>>>(W1, b1, n_nodes);
        edge_gru_kernel<<<740, 128>>>(W2, b2, W3, b3, Wih, Whh, bih, bhh,
                                      (it == 5) ? out : (float*)nullptr, n_nodes);
    }
}

// round 6
// speedup vs baseline: 1.3012x; 1.3012x over previous
#include <cuda_runtime.h>

#define NN 50000
#define NE 800000
#define NB 64

// ---------------- scratch (device globals: allocation-free) ----------------
__device__ __align__(16) float g_node[NN * 32];
__device__ __align__(16) float g_P0[NN * 32];
__device__ __align__(16) float g_Q0[NN * 32];
__device__ __align__(16) float g_P1[NN * 32];
__device__ __align__(16) float g_Q1[NN * 32];
__device__ __align__(16) float g_pvc[NN * 32];
__device__ int   g_cnt[NN];     // zero-init at load; re-zeroed by scan23 each run
__device__ int   g_off[NN + 1];
__device__ int   g_cur[NN];
__device__ int   g_csr[2 * NE];
__device__ int   g_bsum[NB];

// ---------------- prep kernels ----------------
__global__ void count_kernel(const int* __restrict__ e, int n2e) {
    int i = blockIdx.x * blockDim.x + threadIdx.x;
    if (i < n2e) atomicAdd(&g_cnt[e[i]], 1);
}

__global__ void scan1_kernel(int n, int seg) {
    int b = blockIdx.x;
    int beg = b * seg, end = min(beg + seg, n);
    int tid = threadIdx.x;
    int s = 0;
    for (int i = beg + tid; i < end; i += 256) s += g_cnt[i];
    __shared__ int sm[8];
    int lane = tid & 31, w = tid >> 5;
#pragma unroll
    for (int o = 16; o >= 1; o >>= 1) s += __shfl_down_sync(0xffffffffu, s, o);
    if (lane == 0) sm[w] = s;
    __syncthreads();
    if (tid == 0) {
        int t = 0;
#pragma unroll
        for (int k = 0; k < 8; k++) t += sm[k];
        g_bsum[b] = t;
    }
}

// block prefix over g_bsum + per-block scan + write offsets + re-zero g_cnt
__global__ void scan23_kernel(int n, int seg) {
    int b = blockIdx.x, tid = threadIdx.x;
    __shared__ int s_pre;
    if (tid == 0) {
        int t = 0;
        for (int k = 0; k < b; k++) t += g_bsum[k];
        s_pre = t;
    }
    __syncthreads();
    int beg = b * seg, end = min(beg + seg, n);
    int len = max(end - beg, 0);
    int c = (len + 255) / 256;
    int tb = min(beg + tid * c, end), te = min(tb + c, end);
    int s = 0;
    for (int i = tb; i < te; i++) s += g_cnt[i];
    int lane = tid & 31, w = tid >> 5;
    int v = s;
#pragma unroll
    for (int o = 1; o < 32; o <<= 1) {
        int t = __shfl_up_sync(0xffffffffu, v, o);
        if (lane >= o) v += t;
    }
    __shared__ int wt[8], wpre[8];
    if (lane == 31) wt[w] = v;
    __syncthreads();
    if (tid < 8) {
        int x = wt[tid];
#pragma unroll
        for (int o = 1; o < 8; o <<= 1) {
            int t = __shfl_up_sync(0xffu, x, o);
            if (tid >= o) x += t;
        }
        wpre[tid] = x;
    }
    __syncthreads();
    int excl = (v - s) + (w > 0 ? wpre[w - 1] : 0);
    int run = s_pre + excl;
    for (int i = tb; i < te; i++) {
        g_off[i] = run;
        g_cur[i] = run;
        run += g_cnt[i];
    }
    for (int i = tb; i < te; i++) g_cnt[i] = 0;   // ready for next replay
    if (b == gridDim.x - 1 && tid == 255) g_off[n] = run;
}

__global__ void scatter_kernel(const int* __restrict__ e, int nE) {
    int i = blockIdx.x * blockDim.x + threadIdx.x;
    if (i >= 2 * nE) return;
    int src = e[i];
    int dst = (i < nE) ? e[i + nE] : e[i - nE];
    int slot = atomicAdd(&g_cur[src], 1);
    g_csr[slot] = dst;
}

// once: node0 = classes@Win.T + bin ; pvc = pos@W1c.T ; P0,Q0 from node0
__global__ void embed_pq_kernel(const float* __restrict__ classes,
                                const float* __restrict__ pos,
                                const float* __restrict__ Win,
                                const float* __restrict__ bin,
                                const float* __restrict__ W1,
                                const float* __restrict__ b1,
                                int n_nodes) {
    int warp = (blockIdx.x * blockDim.x + threadIdx.x) >> 5;
    int j = threadIdx.x & 31;
    if (warp >= n_nodes) return;
    int u = warp;

    float w[16];
#pragma unroll
    for (int k = 0; k < 16; k++) w[k] = Win[j * 16 + k];
    float c = (j < 16) ? classes[u * 16 + j] : 0.f;
    float acc = bin[j];
#pragma unroll
    for (int k = 0; k < 16; k++)
        acc = fmaf(w[k], __shfl_sync(0xffffffffu, c, k), acc);
    g_node[u * 32 + j] = acc;

    float p0 = pos[u * 3 + 0], p1 = pos[u * 3 + 1], p2 = pos[u * 3 + 2];
    float pv = p0 * W1[j * 67 + 64] + p1 * W1[j * 67 + 65] + p2 * W1[j * 67 + 66];
    g_pvc[u * 32 + j] = pv;

    float p = 0.f, q = 0.f;
#pragma unroll
    for (int k = 0; k < 32; k++) {
        float val = __shfl_sync(0xffffffffu, acc, k);
        p = fmaf(W1[j * 67 + k], val, p);
        q = fmaf(W1[j * 67 + 32 + k], val, q);
    }
    g_P0[u * 32 + j] = p + b1[j] - pv;
    g_Q0[u * 32 + j] = q + pv;
}

// ---------------- fused hot kernel ----------------
// Double-buffered P/Q: reads par-buffer, writes (1-par)-buffer for the NEXT
// iteration. This removes the cross-warp race that broke round 5 (a finished
// warp overwriting Q[v] while another warp still gathers it).
// dynamic smem layout (float offsets):
#define OFF_WI2  8192   // float2[1024]
#define OFF_WIN  10240  // float [1024]
#define OFF_WH2  11264  // float2[1024]
#define OFF_WHN  13312  // float [1024]
#define OFF_W3   14336  // float [1024]
#define OFF_W1AB 15360  // float2[1024]
#define SMEM_BYTES (17408 * 4)

__global__ void __launch_bounds__(256, 3) edge_gru_kernel(
        const float* __restrict__ W1, const float* __restrict__ b1,
        const float* __restrict__ W2, const float* __restrict__ b2,
        const float* __restrict__ W3, const float* __restrict__ b3,
        const float* __restrict__ Wih, const float* __restrict__ Whh,
        const float* __restrict__ bih, const float* __restrict__ bhh,
        float* __restrict__ out, int write_pq, int par, int n_nodes) {
    const float* __restrict__ Pin  = par ? g_P1 : g_P0;
    const float* __restrict__ Qin  = par ? g_Q1 : g_Q0;
    float* __restrict__ Pout = par ? g_P0 : g_P1;
    float* __restrict__ Qout = par ? g_Q0 : g_Q1;

    extern __shared__ float sm[];
    float2* sWi2  = (float2*)(sm + OFF_WI2);
    float*  sWin  = sm + OFF_WIN;
    float2* sWh2  = (float2*)(sm + OFF_WH2);
    float*  sWhn  = sm + OFF_WHN;
    float*  sW3   = sm + OFF_W3;
    float2* sW1ab = (float2*)(sm + OFF_W1AB);

    int tid = threadIdx.x, wl = tid >> 5, j = tid & 31;
    for (int idx = tid; idx < 1024; idx += 256) {
        int k = idx >> 5, jj = idx & 31;
        sWi2[idx]  = make_float2(Wih[jj * 32 + k], Wih[(jj + 32) * 32 + k]);
        sWin[idx]  = Wih[(jj + 64) * 32 + k];
        sWh2[idx]  = make_float2(Whh[jj * 32 + k], Whh[(jj + 32) * 32 + k]);
        sWhn[idx]  = Whh[(jj + 64) * 32 + k];
        sW3[idx]   = W3[jj * 32 + k];
        sW1ab[idx] = make_float2(W1[jj * 67 + k], W1[jj * 67 + 32 + k]);
    }
    __syncthreads();

    float w2[32];
#pragma unroll
    for (int k = 0; k < 32; k++) w2[k] = W2[j * 32 + k];
    float bb2 = b2[j], bb3 = b3[j], bb1 = b1[j];
    float br = bih[j], bz = bih[j + 32], bn = bih[j + 64];
    float cr = bhh[j], cz = bhh[j + 32], cn = bhh[j + 64];

    float (*A)[32] = (float(*)[32])(sm + wl * 1024);
    int sub = j >> 3;       // row subgroup 0..3
    int qcol = j & 7;       // float4 column
    int nw = gridDim.x * 8;

    for (int u = blockIdx.x * 8 + wl; u < n_nodes; u += nw) {
        float pj = Pin[(size_t)u * 32 + j];
        float4 pq4;
        pq4.x = __shfl_sync(0xffffffffu, pj, qcol * 4 + 0);
        pq4.y = __shfl_sync(0xffffffffu, pj, qcol * 4 + 1);
        pq4.z = __shfl_sync(0xffffffffu, pj, qcol * 4 + 2);
        pq4.w = __shfl_sync(0xffffffffu, pj, qcol * 4 + 3);

        int s = g_off[u], e = g_off[u + 1];
        float acc = 0.f;
        int vcur = (s + j < e) ? g_csr[s + j] : 0;

        for (int base = s; base < e; base += 32) {
            int cnt = min(32, e - base);
            int vnext = (base + 32 + j < e) ? g_csr[base + 32 + j] : 0;
            __syncwarp();
            if (cnt == 32) {
#pragma unroll
                for (int it = 0; it < 8; it++) {
                    int row = it * 4 + sub;
                    int vv = __shfl_sync(0xffffffffu, vcur, row);
                    float4 q = *(const float4*)&Qin[(size_t)vv * 32 + qcol * 4];
                    float4 hh;
                    hh.x = fmaxf(pq4.x + q.x, 0.f);
                    hh.y = fmaxf(pq4.y + q.y, 0.f);
                    hh.z = fmaxf(pq4.z + q.z, 0.f);
                    hh.w = fmaxf(pq4.w + q.w, 0.f);
                    *(float4*)&A[row][qcol * 4] = hh;
                }
            } else {
#pragma unroll
                for (int it = 0; it < 8; it++) {
                    int row = it * 4 + sub;
                    int vv = __shfl_sync(0xffffffffu, vcur, row);
                    if (row < cnt) {
                        float4 q = *(const float4*)&Qin[(size_t)vv * 32 + qcol * 4];
                        float4 hh;
                        hh.x = fmaxf(pq4.x + q.x, 0.f);
                        hh.y = fmaxf(pq4.y + q.y, 0.f);
                        hh.z = fmaxf(pq4.z + q.z, 0.f);
                        hh.w = fmaxf(pq4.w + q.w, 0.f);
                        *(float4*)&A[row][qcol * 4] = hh;
                    }
                }
            }
            __syncwarp();
#pragma unroll 4
            for (int t = 0; t < cnt; t++) {
                const float4* row = (const float4*)A[t];
                float h0 = bb2, h1 = 0.f, h2 = 0.f, h3 = 0.f;
#pragma unroll
                for (int c = 0; c < 8; c++) {
                    float4 r = row[c];
                    h0 = fmaf(w2[c * 4 + 0], r.x, h0);
                    h1 = fmaf(w2[c * 4 + 1], r.y, h1);
                    h2 = fmaf(w2[c * 4 + 2], r.z, h2);
                    h3 = fmaf(w2[c * 4 + 3], r.w, h3);
                }
                acc += fmaxf((h0 + h1) + (h2 + h3), 0.f);
            }
            vcur = vnext;
        }

        // layer-3 epilogue (commutes with segment-sum)
        float a = (float)(e - s) * bb3;
#pragma unroll
        for (int k = 0; k < 32; k++)
            a = fmaf(sW3[k * 32 + j], __shfl_sync(0xffffffffu, acc, k), a);

        // GRU (torch gate order r,z,n)
        float h = g_node[(size_t)u * 32 + j];
        float gir = br, giz = bz, gin = bn, ghr = cr, ghz = cz, ghn = cn;
#pragma unroll
        for (int k = 0; k < 32; k++) {
            float xa = __shfl_sync(0xffffffffu, a, k);
            float hb = __shfl_sync(0xffffffffu, h, k);
            float2 wi = sWi2[k * 32 + j];
            float win = sWin[k * 32 + j];
            float2 wh = sWh2[k * 32 + j];
            float whn = sWhn[k * 32 + j];
            gir = fmaf(wi.x, xa, gir); giz = fmaf(wi.y, xa, giz); gin = fmaf(win, xa, gin);
            ghr = fmaf(wh.x, hb, ghr); ghz = fmaf(wh.y, hb, ghz); ghn = fmaf(whn, hb, ghn);
        }
        float r = 1.f / (1.f + expf(-(gir + ghr)));
        float z = 1.f / (1.f + expf(-(giz + ghz)));
        float nv = tanhf(gin + r * ghn);
        float nh = (1.f - z) * nv + z * h;
        g_node[(size_t)u * 32 + j] = nh;
        if (out) out[(size_t)u * 32 + j] = nh;

        // fused P/Q for next iteration -> the OTHER buffer (race-free)
        if (write_pq) {
            float pv = g_pvc[(size_t)u * 32 + j];
            float p = 0.f, q = 0.f;
#pragma unroll
            for (int k = 0; k < 32; k++) {
                float val = __shfl_sync(0xffffffffu, nh, k);
                float2 w1 = sW1ab[k * 32 + j];
                p = fmaf(w1.x, val, p);
                q = fmaf(w1.y, val, q);
            }
            Pout[(size_t)u * 32 + j] = p + bb1 - pv;
            Qout[(size_t)u * 32 + j] = q + pv;
        }
    }
}

// ---------------- launch ----------------
extern "C" void kernel_launch(void* const* d_in, const int* in_sizes, int n_in,
                              void* d_out, int out_size) {
    const float* pos     = (const float*)d_in[0];
    const float* classes = (const float*)d_in[1];
    const int*   edges   = (const int*)d_in[2];
    int wb = (in_sizes[3] == 1) ? 4 : 3;
    const float* Win = (const float*)d_in[wb + 0];
    const float* bin = (const float*)d_in[wb + 1];
    const float* W1  = (const float*)d_in[wb + 2];
    const float* b1  = (const float*)d_in[wb + 3];
    const float* W2  = (const float*)d_in[wb + 4];
    const float* b2  = (const float*)d_in[wb + 5];
    const float* W3  = (const float*)d_in[wb + 6];
    const float* b3  = (const float*)d_in[wb + 7];
    const float* Wih = (const float*)d_in[wb + 8];
    const float* Whh = (const float*)d_in[wb + 9];
    const float* bih = (const float*)d_in[wb + 10];
    const float* bhh = (const float*)d_in[wb + 11];

    int n_nodes = in_sizes[0] / 3;
    int n_edges = in_sizes[2] / 2;
    int n2e = 2 * n_edges;
    float* out = (float*)d_out;
    int seg = (n_nodes + NB - 1) / NB;

    cudaFuncSetAttribute(edge_gru_kernel,
                         cudaFuncAttributeMaxDynamicSharedMemorySize, SMEM_BYTES);

    count_kernel<<<(n2e + 255) / 256, 256>>>(edges, n2e);
    scan1_kernel<<<NB, 256>>>(n_nodes, seg);
    scan23_kernel<<<NB, 256>>>(n_nodes, seg);
    scatter_kernel<<<(n2e + 255) / 256, 256>>>(edges, n_edges);
    embed_pq_kernel<<<(n_nodes + 7) / 8, 256>>>(classes, pos, Win, bin, W1, b1,
                                                n_nodes);

    for (int it = 0; it < 6; ++it) {
        edge_gru_kernel<<<444, 256, SMEM_BYTES>>>(
            W1, b1, W2, b2, W3, b3, Wih, Whh, bih, bhh,
            (it == 5) ? out : (float*)nullptr, (it < 5) ? 1 : 0,
            it & 1, n_nodes);
    }
}

// round 7
// speedup vs baseline: 1.3170x; 1.0121x over previous
#include <cuda_runtime.h>

#define NN 50000
#define NE 800000
#define NB 64

typedef unsigned long long ull;

// ---------------- f32x2 packed helpers ----------------
__device__ __forceinline__ ull pk2(float x, float y) {
    ull r;
    asm("mov.b64 %0, {%1, %2};" : "=l"(r) : "f"(x), "f"(y));
    return r;
}
__device__ __forceinline__ void unpk2(float& x, float& y, ull v) {
    asm("mov.b64 {%0, %1}, %2;" : "=f"(x), "=f"(y) : "l"(v));
}
__device__ __forceinline__ void ffma2(ull& d, ull a, ull b) {
    asm("fma.rn.f32x2 %0, %1, %2, %3;" : "=l"(d) : "l"(a), "l"(b), "l"(d));
}
__device__ __forceinline__ ull add2(ull a, ull b) {
    ull r;
    asm("add.rn.f32x2 %0, %1, %2;" : "=l"(r) : "l"(a), "l"(b));
    return r;
}

// ---------------- scratch (device globals: allocation-free) ----------------
__device__ __align__(16) float g_node[NN * 32];
__device__ __align__(16) float g_P0[NN * 32];
__device__ __align__(16) float g_Q0[NN * 32];
__device__ __align__(16) float g_P1[NN * 32];
__device__ __align__(16) float g_Q1[NN * 32];
__device__ __align__(16) float g_pvc[NN * 32];
__device__ int   g_cnt[NN];     // zero-init at load; re-zeroed by scan23 each run
__device__ int   g_off[NN + 1];
__device__ int   g_cur[NN];
__device__ int   g_csr[2 * NE];
__device__ int   g_bsum[NB];

// ---------------- prep kernels ----------------
__global__ void count_kernel(const int* __restrict__ e, int n2e) {
    int i = blockIdx.x * blockDim.x + threadIdx.x;
    if (i < n2e) atomicAdd(&g_cnt[e[i]], 1);
}

__global__ void scan1_kernel(int n, int seg) {
    int b = blockIdx.x;
    int beg = b * seg, end = min(beg + seg, n);
    int tid = threadIdx.x;
    int s = 0;
    for (int i = beg + tid; i < end; i += 256) s += g_cnt[i];
    __shared__ int sm[8];
    int lane = tid & 31, w = tid >> 5;
#pragma unroll
    for (int o = 16; o >= 1; o >>= 1) s += __shfl_down_sync(0xffffffffu, s, o);
    if (lane == 0) sm[w] = s;
    __syncthreads();
    if (tid == 0) {
        int t = 0;
#pragma unroll
        for (int k = 0; k < 8; k++) t += sm[k];
        g_bsum[b] = t;
    }
}

// block prefix over g_bsum + per-block scan + write offsets + re-zero g_cnt
__global__ void scan23_kernel(int n, int seg) {
    int b = blockIdx.x, tid = threadIdx.x;
    __shared__ int s_pre;
    if (tid == 0) {
        int t = 0;
        for (int k = 0; k < b; k++) t += g_bsum[k];
        s_pre = t;
    }
    __syncthreads();
    int beg = b * seg, end = min(beg + seg, n);
    int len = max(end - beg, 0);
    int c = (len + 255) / 256;
    int tb = min(beg + tid * c, end), te = min(tb + c, end);
    int s = 0;
    for (int i = tb; i < te; i++) s += g_cnt[i];
    int lane = tid & 31, w = tid >> 5;
    int v = s;
#pragma unroll
    for (int o = 1; o < 32; o <<= 1) {
        int t = __shfl_up_sync(0xffffffffu, v, o);
        if (lane >= o) v += t;
    }
    __shared__ int wt[8], wpre[8];
    if (lane == 31) wt[w] = v;
    __syncthreads();
    if (tid < 8) {
        int x = wt[tid];
#pragma unroll
        for (int o = 1; o < 8; o <<= 1) {
            int t = __shfl_up_sync(0xffu, x, o);
            if (tid >= o) x += t;
        }
        wpre[tid] = x;
    }
    __syncthreads();
    int excl = (v - s) + (w > 0 ? wpre[w - 1] : 0);
    int run = s_pre + excl;
    for (int i = tb; i < te; i++) {
        g_off[i] = run;
        g_cur[i] = run;
        run += g_cnt[i];
    }
    for (int i = tb; i < te; i++) g_cnt[i] = 0;   // ready for next replay
    if (b == gridDim.x - 1 && tid == 255) g_off[n] = run;
}

__global__ void scatter_kernel(const int* __restrict__ e, int nE) {
    int i = blockIdx.x * blockDim.x + threadIdx.x;
    if (i >= 2 * nE) return;
    int src = e[i];
    int dst = (i < nE) ? e[i + nE] : e[i - nE];
    int slot = atomicAdd(&g_cur[src], 1);
    g_csr[slot] = dst;
}

// once: node0 = classes@Win.T + bin ; pvc = pos@W1c.T ; P0,Q0 from node0
__global__ void embed_pq_kernel(const float* __restrict__ classes,
                                const float* __restrict__ pos,
                                const float* __restrict__ Win,
                                const float* __restrict__ bin,
                                const float* __restrict__ W1,
                                const float* __restrict__ b1,
                                int n_nodes) {
    int warp = (blockIdx.x * blockDim.x + threadIdx.x) >> 5;
    int j = threadIdx.x & 31;
    if (warp >= n_nodes) return;
    int u = warp;

    float w[16];
#pragma unroll
    for (int k = 0; k < 16; k++) w[k] = Win[j * 16 + k];
    float c = (j < 16) ? classes[u * 16 + j] : 0.f;
    float acc = bin[j];
#pragma unroll
    for (int k = 0; k < 16; k++)
        acc = fmaf(w[k], __shfl_sync(0xffffffffu, c, k), acc);
    g_node[u * 32 + j] = acc;

    float p0 = pos[u * 3 + 0], p1 = pos[u * 3 + 1], p2 = pos[u * 3 + 2];
    float pv = p0 * W1[j * 67 + 64] + p1 * W1[j * 67 + 65] + p2 * W1[j * 67 + 66];
    g_pvc[u * 32 + j] = pv;

    float p = 0.f, q = 0.f;
#pragma unroll
    for (int k = 0; k < 32; k++) {
        float val = __shfl_sync(0xffffffffu, acc, k);
        p = fmaf(W1[j * 67 + k], val, p);
        q = fmaf(W1[j * 67 + 32 + k], val, q);
    }
    g_P0[u * 32 + j] = p + b1[j] - pv;
    g_Q0[u * 32 + j] = q + pv;
}

// ---------------- fused hot kernel ----------------
// Double-buffered P/Q (race-free fusion). pass2 uses packed fma.rn.f32x2:
// 16 FFMA2 + 4 LDS.128 per edge (vs 32 FFMA + 8 LDS.128 scalar).
// dynamic smem layout (float offsets):
#define OFF_WI2  8192   // float2[1024]
#define OFF_WIN  10240  // float [1024]
#define OFF_WH2  11264  // float2[1024]
#define OFF_WHN  13312  // float [1024]
#define OFF_W3   14336  // float [1024]
#define OFF_W1AB 15360  // float2[1024]
#define SMEM_BYTES (17408 * 4)

__global__ void __launch_bounds__(256, 3) edge_gru_kernel(
        const float* __restrict__ W1, const float* __restrict__ b1,
        const float* __restrict__ W2, const float* __restrict__ b2,
        const float* __restrict__ W3, const float* __restrict__ b3,
        const float* __restrict__ Wih, const float* __restrict__ Whh,
        const float* __restrict__ bih, const float* __restrict__ bhh,
        float* __restrict__ out, int write_pq, int par, int n_nodes) {
    const float* __restrict__ Pin  = par ? g_P1 : g_P0;
    const float* __restrict__ Qin  = par ? g_Q1 : g_Q0;
    float* __restrict__ Pout = par ? g_P0 : g_P1;
    float* __restrict__ Qout = par ? g_Q0 : g_Q1;

    extern __shared__ float sm[];
    float2* sWi2  = (float2*)(sm + OFF_WI2);
    float*  sWin  = sm + OFF_WIN;
    float2* sWh2  = (float2*)(sm + OFF_WH2);
    float*  sWhn  = sm + OFF_WHN;
    float*  sW3   = sm + OFF_W3;
    float2* sW1ab = (float2*)(sm + OFF_W1AB);

    int tid = threadIdx.x, wl = tid >> 5, j = tid & 31;
    for (int idx = tid; idx < 1024; idx += 256) {
        int k = idx >> 5, jj = idx & 31;
        sWi2[idx]  = make_float2(Wih[jj * 32 + k], Wih[(jj + 32) * 32 + k]);
        sWin[idx]  = Wih[(jj + 64) * 32 + k];
        sWh2[idx]  = make_float2(Whh[jj * 32 + k], Whh[(jj + 32) * 32 + k]);
        sWhn[idx]  = Whh[(jj + 64) * 32 + k];
        sW3[idx]   = W3[jj * 32 + k];
        sW1ab[idx] = make_float2(W1[jj * 67 + k], W1[jj * 67 + 32 + k]);
    }
    __syncthreads();

    ull w2p[16];
#pragma unroll
    for (int i = 0; i < 16; i++)
        w2p[i] = pk2(W2[j * 32 + 2 * i], W2[j * 32 + 2 * i + 1]);
    float bb2 = b2[j], bb3 = b3[j], bb1 = b1[j];
    float br = bih[j], bz = bih[j + 32], bn = bih[j + 64];
    float cr = bhh[j], cz = bhh[j + 32], cn = bhh[j + 64];

    float (*A)[32] = (float(*)[32])(sm + wl * 1024);
    int sub = j >> 3;       // row subgroup 0..3
    int qcol = j & 7;       // float4 column
    int nw = gridDim.x * 8;

    for (int u = blockIdx.x * 8 + wl; u < n_nodes; u += nw) {
        float pj = Pin[(size_t)u * 32 + j];
        float4 pq4;
        pq4.x = __shfl_sync(0xffffffffu, pj, qcol * 4 + 0);
        pq4.y = __shfl_sync(0xffffffffu, pj, qcol * 4 + 1);
        pq4.z = __shfl_sync(0xffffffffu, pj, qcol * 4 + 2);
        pq4.w = __shfl_sync(0xffffffffu, pj, qcol * 4 + 3);

        int s = g_off[u], e = g_off[u + 1];
        float acc = 0.f;
        int vcur = (s + j < e) ? g_csr[s + j] : 0;

        for (int base = s; base < e; base += 32) {
            int cnt = min(32, e - base);
            int vnext = (base + 32 + j < e) ? g_csr[base + 32 + j] : 0;
            __syncwarp();
            if (cnt == 32) {
#pragma unroll
                for (int it = 0; it < 8; it++) {
                    int row = it * 4 + sub;
                    int vv = __shfl_sync(0xffffffffu, vcur, row);
                    float4 q = *(const float4*)&Qin[(size_t)vv * 32 + qcol * 4];
                    float4 hh;
                    hh.x = fmaxf(pq4.x + q.x, 0.f);
                    hh.y = fmaxf(pq4.y + q.y, 0.f);
                    hh.z = fmaxf(pq4.z + q.z, 0.f);
                    hh.w = fmaxf(pq4.w + q.w, 0.f);
                    *(float4*)&A[row][qcol * 4] = hh;
                }
            } else {
#pragma unroll
                for (int it = 0; it < 8; it++) {
                    int row = it * 4 + sub;
                    int vv = __shfl_sync(0xffffffffu, vcur, row);
                    if (row < cnt) {
                        float4 q = *(const float4*)&Qin[(size_t)vv * 32 + qcol * 4];
                        float4 hh;
                        hh.x = fmaxf(pq4.x + q.x, 0.f);
                        hh.y = fmaxf(pq4.y + q.y, 0.f);
                        hh.z = fmaxf(pq4.z + q.z, 0.f);
                        hh.w = fmaxf(pq4.w + q.w, 0.f);
                        *(float4*)&A[row][qcol * 4] = hh;
                    }
                }
            }
            __syncwarp();
#pragma unroll 4
            for (int t = 0; t < cnt; t++) {
                const ulonglong2* row = (const ulonglong2*)A[t];
                ull a0 = pk2(bb2, 0.f), a1 = 0ull;
#pragma unroll
                for (int c = 0; c < 8; c++) {
                    ulonglong2 r = row[c];
                    ffma2(a0, w2p[2 * c + 0], r.x);
                    ffma2(a1, w2p[2 * c + 1], r.y);
                }
                ull ssum = add2(a0, a1);
                float lo, hi;
                unpk2(lo, hi, ssum);
                acc += fmaxf(lo + hi, 0.f);
            }
            vcur = vnext;
        }

        // layer-3 epilogue (commutes with segment-sum)
        float a = (float)(e - s) * bb3;
#pragma unroll
        for (int k = 0; k < 32; k++)
            a = fmaf(sW3[k * 32 + j], __shfl_sync(0xffffffffu, acc, k), a);

        // GRU (torch gate order r,z,n)
        float h = g_node[(size_t)u * 32 + j];
        float gir = br, giz = bz, gin = bn, ghr = cr, ghz = cz, ghn = cn;
#pragma unroll
        for (int k = 0; k < 32; k++) {
            float xa = __shfl_sync(0xffffffffu, a, k);
            float hb = __shfl_sync(0xffffffffu, h, k);
            float2 wi = sWi2[k * 32 + j];
            float win = sWin[k * 32 + j];
            float2 wh = sWh2[k * 32 + j];
            float whn = sWhn[k * 32 + j];
            gir = fmaf(wi.x, xa, gir); giz = fmaf(wi.y, xa, giz); gin = fmaf(win, xa, gin);
            ghr = fmaf(wh.x, hb, ghr); ghz = fmaf(wh.y, hb, ghz); ghn = fmaf(whn, hb, ghn);
        }
        float r = 1.f / (1.f + expf(-(gir + ghr)));
        float z = 1.f / (1.f + expf(-(giz + ghz)));
        float nv = tanhf(gin + r * ghn);
        float nh = (1.f - z) * nv + z * h;
        g_node[(size_t)u * 32 + j] = nh;
        if (out) out[(size_t)u * 32 + j] = nh;

        // fused P/Q for next iteration -> the OTHER buffer (race-free)
        if (write_pq) {
            float pv = g_pvc[(size_t)u * 32 + j];
            float p = 0.f, q = 0.f;
#pragma unroll
            for (int k = 0; k < 32; k++) {
                float val = __shfl_sync(0xffffffffu, nh, k);
                float2 w1 = sW1ab[k * 32 + j];
                p = fmaf(w1.x, val, p);
                q = fmaf(w1.y, val, q);
            }
            Pout[(size_t)u * 32 + j] = p + bb1 - pv;
            Qout[(size_t)u * 32 + j] = q + pv;
        }
    }
}

// ---------------- launch ----------------
extern "C" void kernel_launch(void* const* d_in, const int* in_sizes, int n_in,
                              void* d_out, int out_size) {
    const float* pos     = (const float*)d_in[0];
    const float* classes = (const float*)d_in[1];
    const int*   edges   = (const int*)d_in[2];
    int wb = (in_sizes[3] == 1) ? 4 : 3;
    const float* Win = (const float*)d_in[wb + 0];
    const float* bin = (const float*)d_in[wb + 1];
    const float* W1  = (const float*)d_in[wb + 2];
    const float* b1  = (const float*)d_in[wb + 3];
    const float* W2  = (const float*)d_in[wb + 4];
    const float* b2  = (const float*)d_in[wb + 5];
    const float* W3  = (const float*)d_in[wb + 6];
    const float* b3  = (const float*)d_in[wb + 7];
    const float* Wih = (const float*)d_in[wb + 8];
    const float* Whh = (const float*)d_in[wb + 9];
    const float* bih = (const float*)d_in[wb + 10];
    const float* bhh = (const float*)d_in[wb + 11];

    int n_nodes = in_sizes[0] / 3;
    int n_edges = in_sizes[2] / 2;
    int n2e = 2 * n_edges;
    float* out = (float*)d_out;
    int seg = (n_nodes + NB - 1) / NB;

    cudaFuncSetAttribute(edge_gru_kernel,
                         cudaFuncAttributeMaxDynamicSharedMemorySize, SMEM_BYTES);

    count_kernel<<<(n2e + 255) / 256, 256>>>(edges, n2e);
    scan1_kernel<<<NB, 256>>>(n_nodes, seg);
    scan23_kernel<<<NB, 256>>>(n_nodes, seg);
    scatter_kernel<<<(n2e + 255) / 256, 256>>>(edges, n_edges);
    embed_pq_kernel<<<(n_nodes + 7) / 8, 256>>>(classes, pos, Win, bin, W1, b1,
                                                n_nodes);

    for (int it = 0; it < 6; ++it) {
        edge_gru_kernel<<<444, 256, SMEM_BYTES>>>(
            W1, b1, W2, b2, W3, b3, Wih, Whh, bih, bhh,
            (it == 5) ? out : (float*)nullptr, (it < 5) ? 1 : 0,
            it & 1, n_nodes);
    }
}

// round 8
// speedup vs baseline: 1.3947x; 1.0590x over previous
#include <cuda_runtime.h>
#include <cstdint>

#define NN 50000
#define NE 800000
#define NB 64

// ---------------- scratch (device globals: allocation-free) ----------------
__device__ __align__(16) float g_node[NN * 32];
__device__ __align__(16) float g_P0[NN * 32];
__device__ __align__(16) float g_Q0[NN * 32];
__device__ __align__(16) float g_P1[NN * 32];
__device__ __align__(16) float g_Q1[NN * 32];
__device__ __align__(16) float g_pvc[NN * 32];
__device__ int   g_cnt[NN];     // zero-init at load; re-zeroed by scan23 each run
__device__ int   g_off[NN + 1];
__device__ int   g_cur[NN];
__device__ int   g_csr[2 * NE];
__device__ int   g_bsum[NB];

// ---------------- helpers ----------------
__device__ __forceinline__ uint32_t tf32c(float x) {
    uint32_t r;
    asm("cvt.rna.tf32.f32 %0, %1;" : "=r"(r) : "f"(x));
    return r;
}
__device__ __forceinline__ void mma_tf32(float& d0, float& d1, float& d2, float& d3,
                                         uint32_t a0, uint32_t a1, uint32_t a2, uint32_t a3,
                                         uint32_t b0, uint32_t b1) {
    asm("mma.sync.aligned.m16n8k8.row.col.f32.tf32.tf32.f32 "
        "{%0,%1,%2,%3}, {%4,%5,%6,%7}, {%8,%9}, {%0,%1,%2,%3};"
        : "+f"(d0), "+f"(d1), "+f"(d2), "+f"(d3)
        : "r"(a0), "r"(a1), "r"(a2), "r"(a3), "r"(b0), "r"(b1));
}

// ---------------- prep kernels ----------------
__global__ void count_kernel(const int* __restrict__ e, int n2e) {
    int i = blockIdx.x * blockDim.x + threadIdx.x;
    if (i < n2e) atomicAdd(&g_cnt[e[i]], 1);
}

__global__ void scan1_kernel(int n, int seg) {
    int b = blockIdx.x;
    int beg = b * seg, end = min(beg + seg, n);
    int tid = threadIdx.x;
    int s = 0;
    for (int i = beg + tid; i < end; i += 256) s += g_cnt[i];
    __shared__ int sm[8];
    int lane = tid & 31, w = tid >> 5;
#pragma unroll
    for (int o = 16; o >= 1; o >>= 1) s += __shfl_down_sync(0xffffffffu, s, o);
    if (lane == 0) sm[w] = s;
    __syncthreads();
    if (tid == 0) {
        int t = 0;
#pragma unroll
        for (int k = 0; k < 8; k++) t += sm[k];
        g_bsum[b] = t;
    }
}

__global__ void scan23_kernel(int n, int seg) {
    int b = blockIdx.x, tid = threadIdx.x;
    __shared__ int s_pre;
    if (tid == 0) {
        int t = 0;
        for (int k = 0; k < b; k++) t += g_bsum[k];
        s_pre = t;
    }
    __syncthreads();
    int beg = b * seg, end = min(beg + seg, n);
    int len = max(end - beg, 0);
    int c = (len + 255) / 256;
    int tb = min(beg + tid * c, end), te = min(tb + c, end);
    int s = 0;
    for (int i = tb; i < te; i++) s += g_cnt[i];
    int lane = tid & 31, w = tid >> 5;
    int v = s;
#pragma unroll
    for (int o = 1; o < 32; o <<= 1) {
        int t = __shfl_up_sync(0xffffffffu, v, o);
        if (lane >= o) v += t;
    }
    __shared__ int wt[8], wpre[8];
    if (lane == 31) wt[w] = v;
    __syncthreads();
    if (tid < 8) {
        int x = wt[tid];
#pragma unroll
        for (int o = 1; o < 8; o <<= 1) {
            int t = __shfl_up_sync(0xffu, x, o);
            if (tid >= o) x += t;
        }
        wpre[tid] = x;
    }
    __syncthreads();
    int excl = (v - s) + (w > 0 ? wpre[w - 1] : 0);
    int run = s_pre + excl;
    for (int i = tb; i < te; i++) {
        g_off[i] = run;
        g_cur[i] = run;
        run += g_cnt[i];
    }
    for (int i = tb; i < te; i++) g_cnt[i] = 0;
    if (b == gridDim.x - 1 && tid == 255) g_off[n] = run;
}

__global__ void scatter_kernel(const int* __restrict__ e, int nE) {
    int i = blockIdx.x * blockDim.x + threadIdx.x;
    if (i >= 2 * nE) return;
    int src = e[i];
    int dst = (i < nE) ? e[i + nE] : e[i - nE];
    int slot = atomicAdd(&g_cur[src], 1);
    g_csr[slot] = dst;
}

// once: node0 = classes@Win.T + bin ; pvc = pos@W1c.T ; P0,Q0 from node0
__global__ void embed_pq_kernel(const float* __restrict__ classes,
                                const float* __restrict__ pos,
                                const float* __restrict__ Win,
                                const float* __restrict__ bin,
                                const float* __restrict__ W1,
                                const float* __restrict__ b1,
                                int n_nodes) {
    int warp = (blockIdx.x * blockDim.x + threadIdx.x) >> 5;
    int j = threadIdx.x & 31;
    if (warp >= n_nodes) return;
    int u = warp;

    float w[16];
#pragma unroll
    for (int k = 0; k < 16; k++) w[k] = Win[j * 16 + k];
    float c = (j < 16) ? classes[u * 16 + j] : 0.f;
    float acc = bin[j];
#pragma unroll
    for (int k = 0; k < 16; k++)
        acc = fmaf(w[k], __shfl_sync(0xffffffffu, c, k), acc);
    g_node[u * 32 + j] = acc;

    float p0 = pos[u * 3 + 0], p1 = pos[u * 3 + 1], p2 = pos[u * 3 + 2];
    float pv = p0 * W1[j * 67 + 64] + p1 * W1[j * 67 + 65] + p2 * W1[j * 67 + 66];
    g_pvc[u * 32 + j] = pv;

    float p = 0.f, q = 0.f;
#pragma unroll
    for (int k = 0; k < 32; k++) {
        float val = __shfl_sync(0xffffffffu, acc, k);
        p = fmaf(W1[j * 67 + k], val, p);
        q = fmaf(W1[j * 67 + 32 + k], val, q);
    }
    g_P0[u * 32 + j] = p + b1[j] - pv;
    g_Q0[u * 32 + j] = q + pv;
}

// ---------------- fused hot kernel (tensor-core pass2) ----------------
// pass1 stores the relu(P+Q) tile in tf32 MMA-fragment layout (swizzled,
// conflict-free). pass2 = 32x HMMA m16n8k8 tf32 per 32-edge chunk.
// Bias b2 added per element pre-relu; zero-padded rows corrected exactly
// via acc -= pad*relu(b2).
#define OFF_WI2  8192   // float2[1024]
#define OFF_WIN  10240  // float [1024]
#define OFF_WH2  11264  // float2[1024]
#define OFF_WHN  13312  // float [1024]
#define OFF_W3   14336  // float [1024]
#define OFF_W1AB 15360  // float2[1024]
#define SMEM_BYTES (17408 * 4)

__global__ void __launch_bounds__(256, 3) edge_gru_kernel(
        const float* __restrict__ W1, const float* __restrict__ b1,
        const float* __restrict__ W2, const float* __restrict__ b2,
        const float* __restrict__ W3, const float* __restrict__ b3,
        const float* __restrict__ Wih, const float* __restrict__ Whh,
        const float* __restrict__ bih, const float* __restrict__ bhh,
        float* __restrict__ out, int write_pq, int par, int n_nodes) {
    const float* __restrict__ Pin  = par ? g_P1 : g_P0;
    const float* __restrict__ Qin  = par ? g_Q1 : g_Q0;
    float* __restrict__ Pout = par ? g_P0 : g_P1;
    float* __restrict__ Qout = par ? g_Q0 : g_Q1;

    extern __shared__ float sm[];
    float2* sWi2  = (float2*)(sm + OFF_WI2);
    float*  sWin  = sm + OFF_WIN;
    float2* sWh2  = (float2*)(sm + OFF_WH2);
    float*  sWhn  = sm + OFF_WHN;
    float*  sW3   = sm + OFF_W3;
    float2* sW1ab = (float2*)(sm + OFF_W1AB);

    int tid = threadIdx.x, wl = tid >> 5, j = tid & 31;
    for (int idx = tid; idx < 1024; idx += 256) {
        int k = idx >> 5, jj = idx & 31;
        sWi2[idx]  = make_float2(Wih[jj * 32 + k], Wih[(jj + 32) * 32 + k]);
        sWin[idx]  = Wih[(jj + 64) * 32 + k];
        sWh2[idx]  = make_float2(Whh[jj * 32 + k], Whh[(jj + 32) * 32 + k]);
        sWhn[idx]  = Whh[(jj + 64) * 32 + k];
        sW3[idx]   = W3[jj * 32 + k];
        sW1ab[idx] = make_float2(W1[jj * 67 + k], W1[jj * 67 + 32 + k]);
    }
    __syncthreads();

    // B fragments (W2^T, col-major k8n8) in tf32, fixed in registers
    uint32_t B0[16], B1[16];
#pragma unroll
    for (int kt = 0; kt < 4; kt++)
#pragma unroll
        for (int nt = 0; nt < 4; nt++) {
            int ncol = nt * 8 + (j >> 2);
            int krow = kt * 8 + (j & 3);
            B0[kt * 4 + nt] = tf32c(W2[ncol * 32 + krow]);
            B1[kt * 4 + nt] = tf32c(W2[ncol * 32 + krow + 4]);
        }
    float b2e[4], b2o[4];
#pragma unroll
    for (int nt = 0; nt < 4; nt++) {
        b2e[nt] = b2[nt * 8 + (j & 3) * 2];
        b2o[nt] = b2[nt * 8 + (j & 3) * 2 + 1];
    }
    float bb2 = b2[j], bb3 = b3[j], bb1 = b1[j];
    float br = bih[j], bz = bih[j + 32], bn = bih[j + 64];
    float cr = bhh[j], cz = bhh[j + 32], cn = bhh[j + 64];

    uint32_t* Aw = (uint32_t*)(sm + wl * 1024);
    float* smf = sm + wl * 1024;
    int sub = j & 3;        // row subgroup 0..3
    int qcol = j >> 2;      // float4 column 0..7
    int permj = (j >> 2) + (j & 3) * 8;   // fragment-read lane permutation
    int nw = gridDim.x * 8;

    for (int u = blockIdx.x * 8 + wl; u < n_nodes; u += nw) {
        float pj = Pin[(size_t)u * 32 + j];
        float4 pq4;
        pq4.x = __shfl_sync(0xffffffffu, pj, qcol * 4 + 0);
        pq4.y = __shfl_sync(0xffffffffu, pj, qcol * 4 + 1);
        pq4.z = __shfl_sync(0xffffffffu, pj, qcol * 4 + 2);
        pq4.w = __shfl_sync(0xffffffffu, pj, qcol * 4 + 3);

        int s = g_off[u], e = g_off[u + 1];
        float acc[8];
#pragma unroll
        for (int r = 0; r < 8; r++) acc[r] = 0.f;
        int vcur = (s + j < e) ? g_csr[s + j] : 0;

        for (int base = s; base < e; base += 32) {
            int cnt = min(32, e - base);
            int vnext = (base + 32 + j < e) ? g_csr[base + 32 + j] : 0;
            __syncwarp();
            // ---- pass1: gather Q rows, relu, store tf32 fragments ----
#pragma unroll
            for (int it = 0; it < 8; it++) {
                int row = it * 4 + sub;
                int vv = __shfl_sync(0xffffffffu, vcur, row);
                float4 q = *(const float4*)&Qin[(size_t)vv * 32 + qcol * 4];
                float h0 = fmaxf(pq4.x + q.x, 0.f);
                float h1 = fmaxf(pq4.y + q.y, 0.f);
                float h2 = fmaxf(pq4.z + q.z, 0.f);
                float h3 = fmaxf(pq4.w + q.w, 0.f);
                if (row >= cnt) { h0 = h1 = h2 = h3 = 0.f; }
                // T = mt*16 + slot_r + 2*qcol ; addr = T*32 + ((row&7)+8i+2T)&31
                int T0 = ((row >> 4) << 4) + ((row >> 3) & 1) + (qcol << 1);
                int bA = T0 * 32;
                int sw = (row & 7) + 2 * T0;
                Aw[bA + ((sw     ) & 31)] = tf32c(h0);
                Aw[bA + ((sw +  8) & 31)] = tf32c(h1);
                Aw[bA + ((sw + 16) & 31)] = tf32c(h2);
                Aw[bA + ((sw + 24) & 31)] = tf32c(h3);
            }
            __syncwarp();
            // ---- pass2: 32x m16n8k8 tf32 MMA ----
#pragma unroll
            for (int mt = 0; mt < 2; mt++) {
                uint32_t a[16];
#pragma unroll
                for (int idx = 0; idx < 16; idx++) {
                    int T = mt * 16 + idx;
                    a[idx] = Aw[T * 32 + ((permj + 2 * T) & 31)];
                }
#pragma unroll
                for (int nt = 0; nt < 4; nt++) {
                    float d0 = 0.f, d1 = 0.f, d2 = 0.f, d3 = 0.f;
#pragma unroll
                    for (int kt = 0; kt < 4; kt++)
                        mma_tf32(d0, d1, d2, d3,
                                 a[kt * 4 + 0], a[kt * 4 + 1],
                                 a[kt * 4 + 2], a[kt * 4 + 3],
                                 B0[kt * 4 + nt], B1[kt * 4 + nt]);
                    acc[nt * 2 + 0] += fmaxf(d0 + b2e[nt], 0.f) + fmaxf(d2 + b2e[nt], 0.f);
                    acc[nt * 2 + 1] += fmaxf(d1 + b2o[nt], 0.f) + fmaxf(d3 + b2o[nt], 0.f);
                }
            }
            vcur = vnext;
        }

        // ---- cross-lane reduce (lanes sharing j&3) + remap to col-per-lane ----
#pragma unroll
        for (int o = 4; o < 32; o <<= 1)
#pragma unroll
            for (int r = 0; r < 8; r++)
                acc[r] += __shfl_xor_sync(0xffffffffu, acc[r], o);
        __syncwarp();
#pragma unroll
        for (int r = 0; r < 8; r++) smf[r * 32 + j] = acc[r];
        __syncwarp();
        float accj = smf[(((j >> 3) << 1) + (j & 1)) * 32 + ((j & 7) >> 1)];

        int deg = e - s;
        int pad = ((deg + 31) & ~31) - deg;
        accj -= (float)pad * fmaxf(bb2, 0.f);

        // layer-3 epilogue (commutes with segment-sum)
        float aval = (float)deg * bb3;
#pragma unroll
        for (int k = 0; k < 32; k++)
            aval = fmaf(sW3[k * 32 + j], __shfl_sync(0xffffffffu, accj, k), aval);

        // GRU (torch gate order r,z,n)
        float h = g_node[(size_t)u * 32 + j];
        float gir = br, giz = bz, gin = bn, ghr = cr, ghz = cz, ghn = cn;
#pragma unroll
        for (int k = 0; k < 32; k++) {
            float xa = __shfl_sync(0xffffffffu, aval, k);
            float hb = __shfl_sync(0xffffffffu, h, k);
            float2 wi = sWi2[k * 32 + j];
            float win = sWin[k * 32 + j];
            float2 wh = sWh2[k * 32 + j];
            float whn = sWhn[k * 32 + j];
            gir = fmaf(wi.x, xa, gir); giz = fmaf(wi.y, xa, giz); gin = fmaf(win, xa, gin);
            ghr = fmaf(wh.x, hb, ghr); ghz = fmaf(wh.y, hb, ghz); ghn = fmaf(whn, hb, ghn);
        }
        float r = 1.f / (1.f + expf(-(gir + ghr)));
        float z = 1.f / (1.f + expf(-(giz + ghz)));
        float nv = tanhf(gin + r * ghn);
        float nh = (1.f - z) * nv + z * h;
        g_node[(size_t)u * 32 + j] = nh;
        if (out) out[(size_t)u * 32 + j] = nh;

        // fused P/Q for next iteration -> the OTHER buffer (race-free)
        if (write_pq) {
            float pv = g_pvc[(size_t)u * 32 + j];
            float p = 0.f, q = 0.f;
#pragma unroll
            for (int k = 0; k < 32; k++) {
                float val = __shfl_sync(0xffffffffu, nh, k);
                float2 w1 = sW1ab[k * 32 + j];
                p = fmaf(w1.x, val, p);
                q = fmaf(w1.y, val, q);
            }
            Pout[(size_t)u * 32 + j] = p + bb1 - pv;
            Qout[(size_t)u * 32 + j] = q + pv;
        }
    }
}

// ---------------- launch ----------------
extern "C" void kernel_launch(void* const* d_in, const int* in_sizes, int n_in,
                              void* d_out, int out_size) {
    const float* pos     = (const float*)d_in[0];
    const float* classes = (const float*)d_in[1];
    const int*   edges   = (const int*)d_in[2];
    int wb = (in_sizes[3] == 1) ? 4 : 3;
    const float* Win = (const float*)d_in[wb + 0];
    const float* bin = (const float*)d_in[wb + 1];
    const float* W1  = (const float*)d_in[wb + 2];
    const float* b1  = (const float*)d_in[wb + 3];
    const float* W2  = (const float*)d_in[wb + 4];
    const float* b2  = (const float*)d_in[wb + 5];
    const float* W3  = (const float*)d_in[wb + 6];
    const float* b3  = (const float*)d_in[wb + 7];
    const float* Wih = (const float*)d_in[wb + 8];
    const float* Whh = (const float*)d_in[wb + 9];
    const float* bih = (const float*)d_in[wb + 10];
    const float* bhh = (const float*)d_in[wb + 11];

    int n_nodes = in_sizes[0] / 3;
    int n_edges = in_sizes[2] / 2;
    int n2e = 2 * n_edges;
    float* out = (float*)d_out;
    int seg = (n_nodes + NB - 1) / NB;

    cudaFuncSetAttribute(edge_gru_kernel,
                         cudaFuncAttributeMaxDynamicSharedMemorySize, SMEM_BYTES);

    count_kernel<<<(n2e + 255) / 256, 256>>>(edges, n2e);
    scan1_kernel<<<NB, 256>>>(n_nodes, seg);
    scan23_kernel<<<NB, 256>>>(n_nodes, seg);
    scatter_kernel<<<(n2e + 255) / 256, 256>>>(edges, n_edges);
    embed_pq_kernel<<<(n_nodes + 7) / 8, 256>>>(classes, pos, Win, bin, W1, b1,
                                                n_nodes);

    for (int it = 0; it < 6; ++it) {
        edge_gru_kernel<<<444, 256, SMEM_BYTES>>>(
            W1, b1, W2, b2, W3, b3, Wih, Whh, bih, bhh,
            (it == 5) ? out : (float*)nullptr, (it < 5) ? 1 : 0,
            it & 1, n_nodes);
    }
}

// round 9
// speedup vs baseline: 1.6881x; 1.2104x over previous
#include <cuda_runtime.h>
#include <cstdint>

#define NN 50000
#define NE 800000
#define NB 64

// ---------------- scratch (device globals: allocation-free) ----------------
__device__ __align__(16) float g_node[NN * 32];
__device__ __align__(16) float g_P[NN * 32];
__device__ __align__(16) float g_Q[NN * 32];
__device__ __align__(16) float g_pvc[NN * 32];
__device__ __align__(16) float g_a[NN * 32];
__device__ int   g_cnt[NN];     // zero-init at load; re-zeroed by scan23 each run
__device__ int   g_off[NN + 1];
__device__ int   g_cur[NN];
__device__ int   g_csr[2 * NE];
__device__ int   g_bsum[NB];

// ---------------- helpers ----------------
__device__ __forceinline__ uint32_t tf32c(float x) {
    uint32_t r;
    asm("cvt.rna.tf32.f32 %0, %1;" : "=r"(r) : "f"(x));
    return r;
}
__device__ __forceinline__ void mma_tf32(float& d0, float& d1, float& d2, float& d3,
                                         uint32_t a0, uint32_t a1, uint32_t a2, uint32_t a3,
                                         uint32_t b0, uint32_t b1) {
    asm("mma.sync.aligned.m16n8k8.row.col.f32.tf32.tf32.f32 "
        "{%0,%1,%2,%3}, {%4,%5,%6,%7}, {%8,%9}, {%0,%1,%2,%3};"
        : "+f"(d0), "+f"(d1), "+f"(d2), "+f"(d3)
        : "r"(a0), "r"(a1), "r"(a2), "r"(a3), "r"(b0), "r"(b1));
}
__device__ __forceinline__ float sigf(float x) {   // NaN-safe fast sigmoid
    return __fdividef(1.f, 1.f + __expf(-x));
}
__device__ __forceinline__ float tanhfast(float x) { // NaN-safe fast tanh
    float ex = __expf(2.f * x);
    return 1.f - __fdividef(2.f, ex + 1.f);
}

// ---------------- prep kernels ----------------
__global__ void count_kernel(const int* __restrict__ e, int n2e) {
    int i = blockIdx.x * blockDim.x + threadIdx.x;
    if (i < n2e) atomicAdd(&g_cnt[e[i]], 1);
}

__global__ void scan1_kernel(int n, int seg) {
    int b = blockIdx.x;
    int beg = b * seg, end = min(beg + seg, n);
    int tid = threadIdx.x;
    int s = 0;
    for (int i = beg + tid; i < end; i += 256) s += g_cnt[i];
    __shared__ int sm[8];
    int lane = tid & 31, w = tid >> 5;
#pragma unroll
    for (int o = 16; o >= 1; o >>= 1) s += __shfl_down_sync(0xffffffffu, s, o);
    if (lane == 0) sm[w] = s;
    __syncthreads();
    if (tid == 0) {
        int t = 0;
#pragma unroll
        for (int k = 0; k < 8; k++) t += sm[k];
        g_bsum[b] = t;
    }
}

__global__ void scan23_kernel(int n, int seg) {
    int b = blockIdx.x, tid = threadIdx.x;
    __shared__ int s_pre;
    if (tid == 0) {
        int t = 0;
        for (int k = 0; k < b; k++) t += g_bsum[k];
        s_pre = t;
    }
    __syncthreads();
    int beg = b * seg, end = min(beg + seg, n);
    int len = max(end - beg, 0);
    int c = (len + 255) / 256;
    int tb = min(beg + tid * c, end), te = min(tb + c, end);
    int s = 0;
    for (int i = tb; i < te; i++) s += g_cnt[i];
    int lane = tid & 31, w = tid >> 5;
    int v = s;
#pragma unroll
    for (int o = 1; o < 32; o <<= 1) {
        int t = __shfl_up_sync(0xffffffffu, v, o);
        if (lane >= o) v += t;
    }
    __shared__ int wt[8], wpre[8];
    if (lane == 31) wt[w] = v;
    __syncthreads();
    if (tid < 8) {
        int x = wt[tid];
#pragma unroll
        for (int o = 1; o < 8; o <<= 1) {
            int t = __shfl_up_sync(0xffu, x, o);
            if (tid >= o) x += t;
        }
        wpre[tid] = x;
    }
    __syncthreads();
    int excl = (v - s) + (w > 0 ? wpre[w - 1] : 0);
    int run = s_pre + excl;
    for (int i = tb; i < te; i++) {
        g_off[i] = run;
        g_cur[i] = run;
        run += g_cnt[i];
    }
    for (int i = tb; i < te; i++) g_cnt[i] = 0;
    if (b == gridDim.x - 1 && tid == 255) g_off[n] = run;
}

__global__ void scatter_kernel(const int* __restrict__ e, int nE) {
    int i = blockIdx.x * blockDim.x + threadIdx.x;
    if (i >= 2 * nE) return;
    int src = e[i];
    int dst = (i < nE) ? e[i + nE] : e[i - nE];
    int slot = atomicAdd(&g_cur[src], 1);
    g_csr[slot] = dst;
}

// once: node0 = classes@Win.T + bin ; pvc = pos@W1c.T ; P,Q from node0
__global__ void embed_pq_kernel(const float* __restrict__ classes,
                                const float* __restrict__ pos,
                                const float* __restrict__ Win,
                                const float* __restrict__ bin,
                                const float* __restrict__ W1,
                                const float* __restrict__ b1,
                                int n_nodes) {
    int warp = (blockIdx.x * blockDim.x + threadIdx.x) >> 5;
    int j = threadIdx.x & 31;
    if (warp >= n_nodes) return;
    int u = warp;

    float w[16];
#pragma unroll
    for (int k = 0; k < 16; k++) w[k] = Win[j * 16 + k];
    float c = (j < 16) ? classes[u * 16 + j] : 0.f;
    float acc = bin[j];
#pragma unroll
    for (int k = 0; k < 16; k++)
        acc = fmaf(w[k], __shfl_sync(0xffffffffu, c, k), acc);
    g_node[u * 32 + j] = acc;

    float p0 = pos[u * 3 + 0], p1 = pos[u * 3 + 1], p2 = pos[u * 3 + 2];
    float pv = p0 * W1[j * 67 + 64] + p1 * W1[j * 67 + 65] + p2 * W1[j * 67 + 66];
    g_pvc[u * 32 + j] = pv;

    float p = 0.f, q = 0.f;
#pragma unroll
    for (int k = 0; k < 32; k++) {
        float val = __shfl_sync(0xffffffffu, acc, k);
        p = fmaf(W1[j * 67 + k], val, p);
        q = fmaf(W1[j * 67 + 32 + k], val, q);
    }
    g_P[u * 32 + j] = p + b1[j] - pv;
    g_Q[u * 32 + j] = q + pv;
}

// ---------------- message-pass kernel (tensor-core pass2) ----------------
// Writes S[u] = sum_edges relu(h2) to g_a. No epilogue here.
__global__ void __launch_bounds__(256, 3) edge_kernel(
        const float* __restrict__ W2, const float* __restrict__ b2,
        int n_nodes) {
    __shared__ float A_s[8][32][32];   // 32KB per-warp tiles
    int tid = threadIdx.x, wl = tid >> 5, j = tid & 31;

    // B fragments (W2^T, col-major k8n8) in tf32, fixed in registers
    uint32_t B0[16], B1[16];
#pragma unroll
    for (int kt = 0; kt < 4; kt++)
#pragma unroll
        for (int nt = 0; nt < 4; nt++) {
            int ncol = nt * 8 + (j >> 2);
            int krow = kt * 8 + (j & 3);
            B0[kt * 4 + nt] = tf32c(W2[ncol * 32 + krow]);
            B1[kt * 4 + nt] = tf32c(W2[ncol * 32 + krow + 4]);
        }
    float b2e[4], b2o[4];
#pragma unroll
    for (int nt = 0; nt < 4; nt++) {
        b2e[nt] = b2[nt * 8 + (j & 3) * 2];
        b2o[nt] = b2[nt * 8 + (j & 3) * 2 + 1];
    }
    float bb2 = b2[j];

    uint32_t* Aw = (uint32_t*)A_s[wl];
    float* smf = &A_s[wl][0][0];
    int sub = j & 3;        // row subgroup 0..3
    int qcol = j >> 2;      // float4 column 0..7
    int permj = (j >> 2) + (j & 3) * 8;   // fragment-read lane permutation
    int nw = gridDim.x * 8;

    for (int u = blockIdx.x * 8 + wl; u < n_nodes; u += nw) {
        float pj = g_P[(size_t)u * 32 + j];
        float4 pq4;
        pq4.x = __shfl_sync(0xffffffffu, pj, qcol * 4 + 0);
        pq4.y = __shfl_sync(0xffffffffu, pj, qcol * 4 + 1);
        pq4.z = __shfl_sync(0xffffffffu, pj, qcol * 4 + 2);
        pq4.w = __shfl_sync(0xffffffffu, pj, qcol * 4 + 3);

        int s = g_off[u], e = g_off[u + 1];
        float acc[8];
#pragma unroll
        for (int r = 0; r < 8; r++) acc[r] = 0.f;
        int vcur = (s + j < e) ? g_csr[s + j] : 0;

        for (int base = s; base < e; base += 32) {
            int cnt = min(32, e - base);
            int vnext = (base + 32 + j < e) ? g_csr[base + 32 + j] : 0;
            __syncwarp();
            // ---- pass1: gather Q rows, relu, store tf32 fragments ----
#pragma unroll
            for (int it = 0; it < 8; it++) {
                int row = it * 4 + sub;
                int vv = __shfl_sync(0xffffffffu, vcur, row);
                float4 q = *(const float4*)&g_Q[(size_t)vv * 32 + qcol * 4];
                float h0 = fmaxf(pq4.x + q.x, 0.f);
                float h1 = fmaxf(pq4.y + q.y, 0.f);
                float h2 = fmaxf(pq4.z + q.z, 0.f);
                float h3 = fmaxf(pq4.w + q.w, 0.f);
                if (row >= cnt) { h0 = h1 = h2 = h3 = 0.f; }
                int T0 = ((row >> 4) << 4) + ((row >> 3) & 1) + (qcol << 1);
                int bA = T0 * 32;
                int sw = (row & 7) + 2 * T0;
                Aw[bA + ((sw     ) & 31)] = tf32c(h0);
                Aw[bA + ((sw +  8) & 31)] = tf32c(h1);
                Aw[bA + ((sw + 16) & 31)] = tf32c(h2);
                Aw[bA + ((sw + 24) & 31)] = tf32c(h3);
            }
            __syncwarp();
            // ---- pass2: 32x m16n8k8 tf32 MMA ----
#pragma unroll
            for (int mt = 0; mt < 2; mt++) {
                uint32_t a[16];
#pragma unroll
                for (int idx = 0; idx < 16; idx++) {
                    int T = mt * 16 + idx;
                    a[idx] = Aw[T * 32 + ((permj + 2 * T) & 31)];
                }
#pragma unroll
                for (int nt = 0; nt < 4; nt++) {
                    float d0 = 0.f, d1 = 0.f, d2 = 0.f, d3 = 0.f;
#pragma unroll
                    for (int kt = 0; kt < 4; kt++)
                        mma_tf32(d0, d1, d2, d3,
                                 a[kt * 4 + 0], a[kt * 4 + 1],
                                 a[kt * 4 + 2], a[kt * 4 + 3],
                                 B0[kt * 4 + nt], B1[kt * 4 + nt]);
                    acc[nt * 2 + 0] += fmaxf(d0 + b2e[nt], 0.f) + fmaxf(d2 + b2e[nt], 0.f);
                    acc[nt * 2 + 1] += fmaxf(d1 + b2o[nt], 0.f) + fmaxf(d3 + b2o[nt], 0.f);
                }
            }
            vcur = vnext;
        }

        // cross-lane reduce + remap to col-per-lane (layout verified round 8)
#pragma unroll
        for (int o = 4; o < 32; o <<= 1)
#pragma unroll
            for (int r = 0; r < 8; r++)
                acc[r] += __shfl_xor_sync(0xffffffffu, acc[r], o);
        __syncwarp();
#pragma unroll
        for (int r = 0; r < 8; r++) smf[r * 32 + j] = acc[r];
        __syncwarp();
        float accj = smf[(((j >> 3) << 1) + (j & 1)) * 32 + ((j & 7) >> 1)];

        int deg = e - s;
        int pad = ((deg + 31) & ~31) - deg;
        accj -= (float)pad * fmaxf(bb2, 0.f);

        g_a[(size_t)u * 32 + j] = accj;
    }
}

// ---------------- batched epilogue kernel: node-per-thread, exact fp32 ----
// a = S@W3^T + deg*b3 ; GRU(a, h) -> nh ; P/Q for next iter. No shuffles.
__global__ void __launch_bounds__(512, 1) gru_kernel(
        const float* __restrict__ W1, const float* __restrict__ b1,
        const float* __restrict__ W3, const float* __restrict__ b3,
        const float* __restrict__ Wih, const float* __restrict__ Whh,
        const float* __restrict__ bih, const float* __restrict__ bhh,
        float* __restrict__ out, int write_pq, int n_nodes) {
    __shared__ float sWih[96 * 32];
    __shared__ float sWhh[96 * 32];
    __shared__ float sW3[32 * 32];
    __shared__ float sW1[64 * 32];   // rows 0..31 = W1a, 32..63 = W1b
    __shared__ float sbih[96], sbhh[96], sb3[32], sb1[32];
    int tid = threadIdx.x;
    for (int i = tid; i < 96 * 32; i += 512) { sWih[i] = Wih[i]; sWhh[i] = Whh[i]; }
    for (int i = tid; i < 32 * 32; i += 512) {
        sW3[i] = W3[i];
        sW1[i] = W1[(i >> 5) * 67 + (i & 31)];
        sW1[1024 + i] = W1[(i >> 5) * 67 + 32 + (i & 31)];
    }
    if (tid < 96) { sbih[tid] = bih[tid]; sbhh[tid] = bhh[tid]; }
    if (tid < 32) { sb3[tid] = b3[tid]; sb1[tid] = b1[tid]; }
    __syncthreads();

    int u = blockIdx.x * 512 + tid;
    if (u >= n_nodes) return;

    // load S
    float S[32];
    {
        const float4* Sg = (const float4*)&g_a[(size_t)u * 32];
#pragma unroll
        for (int c = 0; c < 8; c++) {
            float4 v = Sg[c];
            S[c * 4] = v.x; S[c * 4 + 1] = v.y; S[c * 4 + 2] = v.z; S[c * 4 + 3] = v.w;
        }
    }
    float deg = (float)(g_off[u + 1] - g_off[u]);

    // a = S @ W3^T + deg*b3
    float a[32];
    for (int o = 0; o < 32; o++) {
        const float4* w = (const float4*)&sW3[o * 32];
        float t0 = 0.f, t1 = 0.f;
#pragma unroll
        for (int c = 0; c < 4; c++) {
            float4 wa = w[2 * c], wb = w[2 * c + 1];
            t0 = fmaf(wa.x, S[8 * c + 0], t0); t0 = fmaf(wa.y, S[8 * c + 1], t0);
            t0 = fmaf(wa.z, S[8 * c + 2], t0); t0 = fmaf(wa.w, S[8 * c + 3], t0);
            t1 = fmaf(wb.x, S[8 * c + 4], t1); t1 = fmaf(wb.y, S[8 * c + 5], t1);
            t1 = fmaf(wb.z, S[8 * c + 6], t1); t1 = fmaf(wb.w, S[8 * c + 7], t1);
        }
        a[o] = t0 + t1 + deg * sb3[o];
    }

    // load h
    float h[32];
    {
        const float4* Hg = (const float4*)&g_node[(size_t)u * 32];
#pragma unroll
        for (int c = 0; c < 8; c++) {
            float4 v = Hg[c];
            h[c * 4] = v.x; h[c * 4 + 1] = v.y; h[c * 4 + 2] = v.z; h[c * 4 + 3] = v.w;
        }
    }

    // GRU gates (torch order r,z,n)
    float nh[32];
    for (int o = 0; o < 32; o++) {
        const float4* wr = (const float4*)&sWih[o * 32];
        const float4* wz = (const float4*)&sWih[(o + 32) * 32];
        const float4* wn = (const float4*)&sWih[(o + 64) * 32];
        const float4* vr = (const float4*)&sWhh[o * 32];
        const float4* vz = (const float4*)&sWhh[(o + 32) * 32];
        const float4* vn = (const float4*)&sWhh[(o + 64) * 32];
        float gir = sbih[o], giz = sbih[o + 32], gin = sbih[o + 64];
        float ghr = sbhh[o], ghz = sbhh[o + 32], ghn = sbhh[o + 64];
#pragma unroll
        for (int c = 0; c < 8; c++) {
            float a0 = a[4 * c], a1 = a[4 * c + 1], a2 = a[4 * c + 2], a3 = a[4 * c + 3];
            float h0 = h[4 * c], h1 = h[4 * c + 1], h2 = h[4 * c + 2], h3 = h[4 * c + 3];
            float4 w;
            w = wr[c]; gir = fmaf(w.x, a0, gir); gir = fmaf(w.y, a1, gir);
                       gir = fmaf(w.z, a2, gir); gir = fmaf(w.w, a3, gir);
            w = wz[c]; giz = fmaf(w.x, a0, giz); giz = fmaf(w.y, a1, giz);
                       giz = fmaf(w.z, a2, giz); giz = fmaf(w.w, a3, giz);
            w = wn[c]; gin = fmaf(w.x, a0, gin); gin = fmaf(w.y, a1, gin);
                       gin = fmaf(w.z, a2, gin); gin = fmaf(w.w, a3, gin);
            w = vr[c]; ghr = fmaf(w.x, h0, ghr); ghr = fmaf(w.y, h1, ghr);
                       ghr = fmaf(w.z, h2, ghr); ghr = fmaf(w.w, h3, ghr);
            w = vz[c]; ghz = fmaf(w.x, h0, ghz); ghz = fmaf(w.y, h1, ghz);
                       ghz = fmaf(w.z, h2, ghz); ghz = fmaf(w.w, h3, ghz);
            w = vn[c]; ghn = fmaf(w.x, h0, ghn); ghn = fmaf(w.y, h1, ghn);
                       ghn = fmaf(w.z, h2, ghn); ghn = fmaf(w.w, h3, ghn);
        }
        float r = sigf(gir + ghr);
        float z = sigf(giz + ghz);
        float nv = tanhfast(gin + r * ghn);
        nh[o] = (1.f - z) * nv + z * h[o];
    }

    // write nh
    {
        float4* Ng = (float4*)&g_node[(size_t)u * 32];
#pragma unroll
        for (int c = 0; c < 8; c++)
            Ng[c] = make_float4(nh[4 * c], nh[4 * c + 1], nh[4 * c + 2], nh[4 * c + 3]);
        if (out) {
            float4* Og = (float4*)&out[(size_t)u * 32];
#pragma unroll
            for (int c = 0; c < 8; c++)
                Og[c] = make_float4(nh[4 * c], nh[4 * c + 1], nh[4 * c + 2], nh[4 * c + 3]);
        }
    }

    // P/Q for next iteration
    if (write_pq) {
        const float4* Vg = (const float4*)&g_pvc[(size_t)u * 32];
        float4* Pg = (float4*)&g_P[(size_t)u * 32];
        float4* Qg = (float4*)&g_Q[(size_t)u * 32];
        for (int cb = 0; cb < 8; cb++) {
            float4 pv = Vg[cb];
            float pr[4], qr[4];
#pragma unroll
            for (int t = 0; t < 4; t++) {
                int jj = cb * 4 + t;
                const float4* wa = (const float4*)&sW1[jj * 32];
                const float4* wb = (const float4*)&sW1[(jj + 32) * 32];
                float p = 0.f, q = 0.f;
#pragma unroll
                for (int c = 0; c < 8; c++) {
                    float4 w1a = wa[c], w1b = wb[c];
                    p = fmaf(w1a.x, nh[4 * c], p);     p = fmaf(w1a.y, nh[4 * c + 1], p);
                    p = fmaf(w1a.z, nh[4 * c + 2], p); p = fmaf(w1a.w, nh[4 * c + 3], p);
                    q = fmaf(w1b.x, nh[4 * c], q);     q = fmaf(w1b.y, nh[4 * c + 1], q);
                    q = fmaf(w1b.z, nh[4 * c + 2], q); q = fmaf(w1b.w, nh[4 * c + 3], q);
                }
                pr[t] = p + sb1[jj];
                qr[t] = q;
            }
            Pg[cb] = make_float4(pr[0] - pv.x, pr[1] - pv.y, pr[2] - pv.z, pr[3] - pv.w);
            Qg[cb] = make_float4(qr[0] + pv.x, qr[1] + pv.y, qr[2] + pv.z, qr[3] + pv.w);
        }
    }
}

// ---------------- launch ----------------
extern "C" void kernel_launch(void* const* d_in, const int* in_sizes, int n_in,
                              void* d_out, int out_size) {
    const float* pos     = (const float*)d_in[0];
    const float* classes = (const float*)d_in[1];
    const int*   edges   = (const int*)d_in[2];
    int wb = (in_sizes[3] == 1) ? 4 : 3;
    const float* Win = (const float*)d_in[wb + 0];
    const float* bin = (const float*)d_in[wb + 1];
    const float* W1  = (const float*)d_in[wb + 2];
    const float* b1  = (const float*)d_in[wb + 3];
    const float* W2  = (const float*)d_in[wb + 4];
    const float* b2  = (const float*)d_in[wb + 5];
    const float* W3  = (const float*)d_in[wb + 6];
    const float* b3  = (const float*)d_in[wb + 7];
    const float* Wih = (const float*)d_in[wb + 8];
    const float* Whh = (const float*)d_in[wb + 9];
    const float* bih = (const float*)d_in[wb + 10];
    const float* bhh = (const float*)d_in[wb + 11];

    int n_nodes = in_sizes[0] / 3;
    int n_edges = in_sizes[2] / 2;
    int n2e = 2 * n_edges;
    float* out = (float*)d_out;
    int seg = (n_nodes + NB - 1) / NB;

    count_kernel<<<(n2e + 255) / 256, 256>>>(edges, n2e);
    scan1_kernel<<<NB, 256>>>(n_nodes, seg);
    scan23_kernel<<<NB, 256>>>(n_nodes, seg);
    scatter_kernel<<<(n2e + 255) / 256, 256>>>(edges, n_edges);
    embed_pq_kernel<<<(n_nodes + 7) / 8, 256>>>(classes, pos, Win, bin, W1, b1,
                                                n_nodes);

    int gru_grid = (n_nodes + 511) / 512;
    for (int it = 0; it < 6; ++it) {
        edge_kernel<<<444, 256>>>(W2, b2, n_nodes);
        gru_kernel<<<gru_grid, 512>>>(
            W1, b1, W3, b3, Wih, Whh, bih, bhh,
            (it == 5) ? out : (float*)nullptr, (it < 5) ? 1 : 0, n_nodes);
    }
}

// round 10
// speedup vs baseline: 1.7543x; 1.0392x over previous
#include <cuda_runtime.h>
#include <cstdint>

#define NN 50000
#define NE 800000
#define NB 64

// ---------------- scratch (device globals: allocation-free) ----------------
__device__ __align__(16) float g_node[NN * 32];
__device__ __align__(16) float g_P[NN * 32];
__device__ __align__(16) float g_Q[NN * 32];
__device__ __align__(16) float g_pvc[NN * 32];
__device__ __align__(16) float g_a[NN * 32];
__device__ int   g_cnt[NN];     // zero-init at load; re-zeroed by scan23 each run
__device__ int   g_off[NN + 1];
__device__ int   g_cur[NN];
__device__ int   g_csr[2 * NE];
__device__ int   g_bsum[NB];

// ---------------- helpers ----------------
__device__ __forceinline__ uint32_t tf32c(float x) {
    uint32_t r;
    asm("cvt.rna.tf32.f32 %0, %1;" : "=r"(r) : "f"(x));
    return r;
}
__device__ __forceinline__ void mma_tf32(float& d0, float& d1, float& d2, float& d3,
                                         uint32_t a0, uint32_t a1, uint32_t a2, uint32_t a3,
                                         uint32_t b0, uint32_t b1) {
    asm("mma.sync.aligned.m16n8k8.row.col.f32.tf32.tf32.f32 "
        "{%0,%1,%2,%3}, {%4,%5,%6,%7}, {%8,%9}, {%0,%1,%2,%3};"
        : "+f"(d0), "+f"(d1), "+f"(d2), "+f"(d3)
        : "r"(a0), "r"(a1), "r"(a2), "r"(a3), "r"(b0), "r"(b1));
}
__device__ __forceinline__ float sigf(float x) {
    return __fdividef(1.f, 1.f + __expf(-x));
}
__device__ __forceinline__ float tanhfast(float x) {
    float ex = __expf(2.f * x);
    return 1.f - __fdividef(2.f, ex + 1.f);
}

// ---------------- prep kernels ----------------
__global__ void count_kernel(const int* __restrict__ e, int n2e) {
    int i = blockIdx.x * blockDim.x + threadIdx.x;
    if (i < n2e) atomicAdd(&g_cnt[e[i]], 1);
}

__global__ void scan1_kernel(int n, int seg) {
    int b = blockIdx.x;
    int beg = b * seg, end = min(beg + seg, n);
    int tid = threadIdx.x;
    int s = 0;
    for (int i = beg + tid; i < end; i += 256) s += g_cnt[i];
    __shared__ int sm[8];
    int lane = tid & 31, w = tid >> 5;
#pragma unroll
    for (int o = 16; o >= 1; o >>= 1) s += __shfl_down_sync(0xffffffffu, s, o);
    if (lane == 0) sm[w] = s;
    __syncthreads();
    if (tid == 0) {
        int t = 0;
#pragma unroll
        for (int k = 0; k < 8; k++) t += sm[k];
        g_bsum[b] = t;
    }
}

__global__ void scan23_kernel(int n, int seg) {
    int b = blockIdx.x, tid = threadIdx.x;
    __shared__ int s_pre;
    if (tid == 0) {
        int t = 0;
        for (int k = 0; k < b; k++) t += g_bsum[k];
        s_pre = t;
    }
    __syncthreads();
    int beg = b * seg, end = min(beg + seg, n);
    int len = max(end - beg, 0);
    int c = (len + 255) / 256;
    int tb = min(beg + tid * c, end), te = min(tb + c, end);
    int s = 0;
    for (int i = tb; i < te; i++) s += g_cnt[i];
    int lane = tid & 31, w = tid >> 5;
    int v = s;
#pragma unroll
    for (int o = 1; o < 32; o <<= 1) {
        int t = __shfl_up_sync(0xffffffffu, v, o);
        if (lane >= o) v += t;
    }
    __shared__ int wt[8], wpre[8];
    if (lane == 31) wt[w] = v;
    __syncthreads();
    if (tid < 8) {
        int x = wt[tid];
#pragma unroll
        for (int o = 1; o < 8; o <<= 1) {
            int t = __shfl_up_sync(0xffu, x, o);
            if (tid >= o) x += t;
        }
        wpre[tid] = x;
    }
    __syncthreads();
    int excl = (v - s) + (w > 0 ? wpre[w - 1] : 0);
    int run = s_pre + excl;
    for (int i = tb; i < te; i++) {
        g_off[i] = run;
        g_cur[i] = run;
        run += g_cnt[i];
    }
    for (int i = tb; i < te; i++) g_cnt[i] = 0;
    if (b == gridDim.x - 1 && tid == 255) g_off[n] = run;
}

__global__ void scatter_kernel(const int* __restrict__ e, int nE) {
    int i = blockIdx.x * blockDim.x + threadIdx.x;
    if (i >= 2 * nE) return;
    int src = e[i];
    int dst = (i < nE) ? e[i + nE] : e[i - nE];
    int slot = atomicAdd(&g_cur[src], 1);
    g_csr[slot] = dst;
}

// once: node0 = classes@Win.T + bin ; pvc = pos@W1c.T ; P,Q from node0
__global__ void embed_pq_kernel(const float* __restrict__ classes,
                                const float* __restrict__ pos,
                                const float* __restrict__ Win,
                                const float* __restrict__ bin,
                                const float* __restrict__ W1,
                                const float* __restrict__ b1,
                                int n_nodes) {
    int warp = (blockIdx.x * blockDim.x + threadIdx.x) >> 5;
    int j = threadIdx.x & 31;
    if (warp >= n_nodes) return;
    int u = warp;

    float w[16];
#pragma unroll
    for (int k = 0; k < 16; k++) w[k] = Win[j * 16 + k];
    float c = (j < 16) ? classes[u * 16 + j] : 0.f;
    float acc = bin[j];
#pragma unroll
    for (int k = 0; k < 16; k++)
        acc = fmaf(w[k], __shfl_sync(0xffffffffu, c, k), acc);
    g_node[u * 32 + j] = acc;

    float p0 = pos[u * 3 + 0], p1 = pos[u * 3 + 1], p2 = pos[u * 3 + 2];
    float pv = p0 * W1[j * 67 + 64] + p1 * W1[j * 67 + 65] + p2 * W1[j * 67 + 66];
    g_pvc[u * 32 + j] = pv;

    float p = 0.f, q = 0.f;
#pragma unroll
    for (int k = 0; k < 32; k++) {
        float val = __shfl_sync(0xffffffffu, acc, k);
        p = fmaf(W1[j * 67 + k], val, p);
        q = fmaf(W1[j * 67 + 32 + k], val, q);
    }
    g_P[u * 32 + j] = p + b1[j] - pv;
    g_Q[u * 32 + j] = q + pv;
}

// ---------------- message-pass kernel (m16 tiles, paired sub-chunks) ----
// S[u] = sum_edges relu(h2) -> g_a. 16-row tiles cut padding from ~45% to
// ~12%; two tiles (A/B) share one 32-lane CSR read and their gathers
// overlap before either pass2 runs.
__global__ void __launch_bounds__(256, 3) edge_kernel(
        const float* __restrict__ W2, const float* __restrict__ b2,
        int n_nodes) {
    __shared__ float A_s[8][2][16][32];   // 32KB: per-warp tile pair
    int tid = threadIdx.x, wl = tid >> 5, j = tid & 31;

    // B fragments (W2^T, col-major k8n8) in tf32, fixed in registers
    uint32_t B0[16], B1[16];
#pragma unroll
    for (int kt = 0; kt < 4; kt++)
#pragma unroll
        for (int nt = 0; nt < 4; nt++) {
            int ncol = nt * 8 + (j >> 2);
            int krow = kt * 8 + (j & 3);
            B0[kt * 4 + nt] = tf32c(W2[ncol * 32 + krow]);
            B1[kt * 4 + nt] = tf32c(W2[ncol * 32 + krow + 4]);
        }
    float b2e[4], b2o[4];
#pragma unroll
    for (int nt = 0; nt < 4; nt++) {
        b2e[nt] = b2[nt * 8 + (j & 3) * 2];
        b2o[nt] = b2[nt * 8 + (j & 3) * 2 + 1];
    }
    float bb2 = b2[j];

    uint32_t* AwA = (uint32_t*)A_s[wl][0];
    uint32_t* AwB = (uint32_t*)A_s[wl][1];
    float* smf = &A_s[wl][0][0][0];
    int sub = j & 3;        // row subgroup 0..3
    int qcol = j >> 2;      // float4 column 0..7
    int permj = (j >> 2) + (j & 3) * 8;   // fragment-read lane permutation
    int nw = gridDim.x * 8;

    for (int u = blockIdx.x * 8 + wl; u < n_nodes; u += nw) {
        float pj = g_P[(size_t)u * 32 + j];
        float4 pq4;
        pq4.x = __shfl_sync(0xffffffffu, pj, qcol * 4 + 0);
        pq4.y = __shfl_sync(0xffffffffu, pj, qcol * 4 + 1);
        pq4.z = __shfl_sync(0xffffffffu, pj, qcol * 4 + 2);
        pq4.w = __shfl_sync(0xffffffffu, pj, qcol * 4 + 3);

        int s = g_off[u], e = g_off[u + 1];
        float acc[8];
#pragma unroll
        for (int r = 0; r < 8; r++) acc[r] = 0.f;
        int vcur = (s + j < e) ? g_csr[s + j] : 0;

        for (int base = s; base < e; base += 32) {
            int cnt = min(32, e - base);
            bool hasB = cnt > 16;
            int vnext = (base + 32 + j < e) ? g_csr[base + 32 + j] : 0;
            __syncwarp();
            // ---- pass1 tile A: rows 0..15 ----
#pragma unroll
            for (int it = 0; it < 4; it++) {
                int row = it * 4 + sub;
                int vv = __shfl_sync(0xffffffffu, vcur, row);
                float4 q = *(const float4*)&g_Q[(size_t)vv * 32 + qcol * 4];
                float h0 = fmaxf(pq4.x + q.x, 0.f);
                float h1 = fmaxf(pq4.y + q.y, 0.f);
                float h2 = fmaxf(pq4.z + q.z, 0.f);
                float h3 = fmaxf(pq4.w + q.w, 0.f);
                if (row >= cnt) { h0 = h1 = h2 = h3 = 0.f; }
                int T0 = ((row >> 3) & 1) + (qcol << 1);
                int bA = T0 * 32;
                int sw = (row & 7) + 2 * T0;
                AwA[bA + ((sw     ) & 31)] = tf32c(h0);
                AwA[bA + ((sw +  8) & 31)] = tf32c(h1);
                AwA[bA + ((sw + 16) & 31)] = tf32c(h2);
                AwA[bA + ((sw + 24) & 31)] = tf32c(h3);
            }
            // ---- pass1 tile B: rows 16..31 (gathers overlap A's) ----
            if (hasB) {
#pragma unroll
                for (int it = 0; it < 4; it++) {
                    int row = it * 4 + sub;
                    int vv = __shfl_sync(0xffffffffu, vcur, 16 + row);
                    float4 q = *(const float4*)&g_Q[(size_t)vv * 32 + qcol * 4];
                    float h0 = fmaxf(pq4.x + q.x, 0.f);
                    float h1 = fmaxf(pq4.y + q.y, 0.f);
                    float h2 = fmaxf(pq4.z + q.z, 0.f);
                    float h3 = fmaxf(pq4.w + q.w, 0.f);
                    if (16 + row >= cnt) { h0 = h1 = h2 = h3 = 0.f; }
                    int T0 = ((row >> 3) & 1) + (qcol << 1);
                    int bA = T0 * 32;
                    int sw = (row & 7) + 2 * T0;
                    AwB[bA + ((sw     ) & 31)] = tf32c(h0);
                    AwB[bA + ((sw +  8) & 31)] = tf32c(h1);
                    AwB[bA + ((sw + 16) & 31)] = tf32c(h2);
                    AwB[bA + ((sw + 24) & 31)] = tf32c(h3);
                }
            }
            __syncwarp();
            // ---- pass2 tile A ----
            {
                uint32_t a[16];
#pragma unroll
                for (int idx = 0; idx < 16; idx++)
                    a[idx] = AwA[idx * 32 + ((permj + 2 * idx) & 31)];
#pragma unroll
                for (int nt = 0; nt < 4; nt++) {
                    float d0 = 0.f, d1 = 0.f, d2 = 0.f, d3 = 0.f;
#pragma unroll
                    for (int kt = 0; kt < 4; kt++)
                        mma_tf32(d0, d1, d2, d3,
                                 a[kt * 4 + 0], a[kt * 4 + 1],
                                 a[kt * 4 + 2], a[kt * 4 + 3],
                                 B0[kt * 4 + nt], B1[kt * 4 + nt]);
                    acc[nt * 2 + 0] += fmaxf(d0 + b2e[nt], 0.f) + fmaxf(d2 + b2e[nt], 0.f);
                    acc[nt * 2 + 1] += fmaxf(d1 + b2o[nt], 0.f) + fmaxf(d3 + b2o[nt], 0.f);
                }
            }
            // ---- pass2 tile B ----
            if (hasB) {
                uint32_t a[16];
#pragma unroll
                for (int idx = 0; idx < 16; idx++)
                    a[idx] = AwB[idx * 32 + ((permj + 2 * idx) & 31)];
#pragma unroll
                for (int nt = 0; nt < 4; nt++) {
                    float d0 = 0.f, d1 = 0.f, d2 = 0.f, d3 = 0.f;
#pragma unroll
                    for (int kt = 0; kt < 4; kt++)
                        mma_tf32(d0, d1, d2, d3,
                                 a[kt * 4 + 0], a[kt * 4 + 1],
                                 a[kt * 4 + 2], a[kt * 4 + 3],
                                 B0[kt * 4 + nt], B1[kt * 4 + nt]);
                    acc[nt * 2 + 0] += fmaxf(d0 + b2e[nt], 0.f) + fmaxf(d2 + b2e[nt], 0.f);
                    acc[nt * 2 + 1] += fmaxf(d1 + b2o[nt], 0.f) + fmaxf(d3 + b2o[nt], 0.f);
                }
            }
            vcur = vnext;
        }

        // cross-lane reduce + remap to col-per-lane (layout verified round 8)
#pragma unroll
        for (int o = 4; o < 32; o <<= 1)
#pragma unroll
            for (int r = 0; r < 8; r++)
                acc[r] += __shfl_xor_sync(0xffffffffu, acc[r], o);
        __syncwarp();
#pragma unroll
        for (int r = 0; r < 8; r++) smf[r * 32 + j] = acc[r];
        __syncwarp();
        float accj = smf[(((j >> 3) << 1) + (j & 1)) * 32 + ((j & 7) >> 1)];

        int deg = e - s;
        int pad = ((deg + 15) & ~15) - deg;
        accj -= (float)pad * fmaxf(bb2, 0.f);

        g_a[(size_t)u * 32 + j] = accj;
    }
}

// ---------------- batched epilogue kernel: node-per-thread, exact fp32 ----
__global__ void __launch_bounds__(512, 1) gru_kernel(
        const float* __restrict__ W1, const float* __restrict__ b1,
        const float* __restrict__ W3, const float* __restrict__ b3,
        const float* __restrict__ Wih, const float* __restrict__ Whh,
        const float* __restrict__ bih, const float* __restrict__ bhh,
        float* __restrict__ out, int write_pq, int n_nodes) {
    __shared__ float sWih[96 * 32];
    __shared__ float sWhh[96 * 32];
    __shared__ float sW3[32 * 32];
    __shared__ float sW1[64 * 32];   // rows 0..31 = W1a, 32..63 = W1b
    __shared__ float sbih[96], sbhh[96], sb3[32], sb1[32];
    int tid = threadIdx.x;
    for (int i = tid; i < 96 * 32; i += 512) { sWih[i] = Wih[i]; sWhh[i] = Whh[i]; }
    for (int i = tid; i < 32 * 32; i += 512) {
        sW3[i] = W3[i];
        sW1[i] = W1[(i >> 5) * 67 + (i & 31)];
        sW1[1024 + i] = W1[(i >> 5) * 67 + 32 + (i & 31)];
    }
    if (tid < 96) { sbih[tid] = bih[tid]; sbhh[tid] = bhh[tid]; }
    if (tid < 32) { sb3[tid] = b3[tid]; sb1[tid] = b1[tid]; }
    __syncthreads();

    int u = blockIdx.x * 512 + tid;
    if (u >= n_nodes) return;

    float S[32];
    {
        const float4* Sg = (const float4*)&g_a[(size_t)u * 32];
#pragma unroll
        for (int c = 0; c < 8; c++) {
            float4 v = Sg[c];
            S[c * 4] = v.x; S[c * 4 + 1] = v.y; S[c * 4 + 2] = v.z; S[c * 4 + 3] = v.w;
        }
    }
    float deg = (float)(g_off[u + 1] - g_off[u]);

    float a[32];
    for (int o = 0; o < 32; o++) {
        const float4* w = (const float4*)&sW3[o * 32];
        float t0 = 0.f, t1 = 0.f;
#pragma unroll
        for (int c = 0; c < 4; c++) {
            float4 wa = w[2 * c], wb = w[2 * c + 1];
            t0 = fmaf(wa.x, S[8 * c + 0], t0); t0 = fmaf(wa.y, S[8 * c + 1], t0);
            t0 = fmaf(wa.z, S[8 * c + 2], t0); t0 = fmaf(wa.w, S[8 * c + 3], t0);
            t1 = fmaf(wb.x, S[8 * c + 4], t1); t1 = fmaf(wb.y, S[8 * c + 5], t1);
            t1 = fmaf(wb.z, S[8 * c + 6], t1); t1 = fmaf(wb.w, S[8 * c + 7], t1);
        }
        a[o] = t0 + t1 + deg * sb3[o];
    }

    float h[32];
    {
        const float4* Hg = (const float4*)&g_node[(size_t)u * 32];
#pragma unroll
        for (int c = 0; c < 8; c++) {
            float4 v = Hg[c];
            h[c * 4] = v.x; h[c * 4 + 1] = v.y; h[c * 4 + 2] = v.z; h[c * 4 + 3] = v.w;
        }
    }

    float nh[32];
    for (int o = 0; o < 32; o++) {
        const float4* wr = (const float4*)&sWih[o * 32];
        const float4* wz = (const float4*)&sWih[(o + 32) * 32];
        const float4* wn = (const float4*)&sWih[(o + 64) * 32];
        const float4* vr = (const float4*)&sWhh[o * 32];
        const float4* vz = (const float4*)&sWhh[(o + 32) * 32];
        const float4* vn = (const float4*)&sWhh[(o + 64) * 32];
        float gir = sbih[o], giz = sbih[o + 32], gin = sbih[o + 64];
        float ghr = sbhh[o], ghz = sbhh[o + 32], ghn = sbhh[o + 64];
#pragma unroll
        for (int c = 0; c < 8; c++) {
            float a0 = a[4 * c], a1 = a[4 * c + 1], a2 = a[4 * c + 2], a3 = a[4 * c + 3];
            float h0 = h[4 * c], h1 = h[4 * c + 1], h2 = h[4 * c + 2], h3 = h[4 * c + 3];
            float4 w;
            w = wr[c]; gir = fmaf(w.x, a0, gir); gir = fmaf(w.y, a1, gir);
                       gir = fmaf(w.z, a2, gir); gir = fmaf(w.w, a3, gir);
            w = wz[c]; giz = fmaf(w.x, a0, giz); giz = fmaf(w.y, a1, giz);
                       giz = fmaf(w.z, a2, giz); giz = fmaf(w.w, a3, giz);
            w = wn[c]; gin = fmaf(w.x, a0, gin); gin = fmaf(w.y, a1, gin);
                       gin = fmaf(w.z, a2, gin); gin = fmaf(w.w, a3, gin);
            w = vr[c]; ghr = fmaf(w.x, h0, ghr); ghr = fmaf(w.y, h1, ghr);
                       ghr = fmaf(w.z, h2, ghr); ghr = fmaf(w.w, h3, ghr);
            w = vz[c]; ghz = fmaf(w.x, h0, ghz); ghz = fmaf(w.y, h1, ghz);
                       ghz = fmaf(w.z, h2, ghz); ghz = fmaf(w.w, h3, ghz);
            w = vn[c]; ghn = fmaf(w.x, h0, ghn); ghn = fmaf(w.y, h1, ghn);
                       ghn = fmaf(w.z, h2, ghn); ghn = fmaf(w.w, h3, ghn);
        }
        float r = sigf(gir + ghr);
        float z = sigf(giz + ghz);
        float nv = tanhfast(gin + r * ghn);
        nh[o] = (1.f - z) * nv + z * h[o];
    }

    {
        float4* Ng = (float4*)&g_node[(size_t)u * 32];
#pragma unroll
        for (int c = 0; c < 8; c++)
            Ng[c] = make_float4(nh[4 * c], nh[4 * c + 1], nh[4 * c + 2], nh[4 * c + 3]);
        if (out) {
            float4* Og = (float4*)&out[(size_t)u * 32];
#pragma unroll
            for (int c = 0; c < 8; c++)
                Og[c] = make_float4(nh[4 * c], nh[4 * c + 1], nh[4 * c + 2], nh[4 * c + 3]);
        }
    }

    if (write_pq) {
        const float4* Vg = (const float4*)&g_pvc[(size_t)u * 32];
        float4* Pg = (float4*)&g_P[(size_t)u * 32];
        float4* Qg = (float4*)&g_Q[(size_t)u * 32];
        for (int cb = 0; cb < 8; cb++) {
            float4 pv = Vg[cb];
            float pr[4], qr[4];
#pragma unroll
            for (int t = 0; t < 4; t++) {
                int jj = cb * 4 + t;
                const float4* wa = (const float4*)&sW1[jj * 32];
                const float4* wb = (const float4*)&sW1[(jj + 32) * 32];
                float p = 0.f, q = 0.f;
#pragma unroll
                for (int c = 0; c < 8; c++) {
                    float4 w1a = wa[c], w1b = wb[c];
                    p = fmaf(w1a.x, nh[4 * c], p);     p = fmaf(w1a.y, nh[4 * c + 1], p);
                    p = fmaf(w1a.z, nh[4 * c + 2], p); p = fmaf(w1a.w, nh[4 * c + 3], p);
                    q = fmaf(w1b.x, nh[4 * c], q);     q = fmaf(w1b.y, nh[4 * c + 1], q);
                    q = fmaf(w1b.z, nh[4 * c + 2], q); q = fmaf(w1b.w, nh[4 * c + 3], q);
                }
                pr[t] = p + sb1[jj];
                qr[t] = q;
            }
            Pg[cb] = make_float4(pr[0] - pv.x, pr[1] - pv.y, pr[2] - pv.z, pr[3] - pv.w);
            Qg[cb] = make_float4(qr[0] + pv.x, qr[1] + pv.y, qr[2] + pv.z, qr[3] + pv.w);
        }
    }
}

// ---------------- launch ----------------
extern "C" void kernel_launch(void* const* d_in, const int* in_sizes, int n_in,
                              void* d_out, int out_size) {
    const float* pos     = (const float*)d_in[0];
    const float* classes = (const float*)d_in[1];
    const int*   edges   = (const int*)d_in[2];
    int wb = (in_sizes[3] == 1) ? 4 : 3;
    const float* Win = (const float*)d_in[wb + 0];
    const float* bin = (const float*)d_in[wb + 1];
    const float* W1  = (const float*)d_in[wb + 2];
    const float* b1  = (const float*)d_in[wb + 3];
    const float* W2  = (const float*)d_in[wb + 4];
    const float* b2  = (const float*)d_in[wb + 5];
    const float* W3  = (const float*)d_in[wb + 6];
    const float* b3  = (const float*)d_in[wb + 7];
    const float* Wih = (const float*)d_in[wb + 8];
    const float* Whh = (const float*)d_in[wb + 9];
    const float* bih = (const float*)d_in[wb + 10];
    const float* bhh = (const float*)d_in[wb + 11];

    int n_nodes = in_sizes[0] / 3;
    int n_edges = in_sizes[2] / 2;
    int n2e = 2 * n_edges;
    float* out = (float*)d_out;
    int seg = (n_nodes + NB - 1) / NB;

    count_kernel<<<(n2e + 255) / 256, 256>>>(edges, n2e);
    scan1_kernel<<<NB, 256>>>(n_nodes, seg);
    scan23_kernel<<<NB, 256>>>(n_nodes, seg);
    scatter_kernel<<<(n2e + 255) / 256, 256>>>(edges, n_edges);
    embed_pq_kernel<<<(n_nodes + 7) / 8, 256>>>(classes, pos, Win, bin, W1, b1,
                                                n_nodes);

    int gru_grid = (n_nodes + 511) / 512;
    for (int it = 0; it < 6; ++it) {
        edge_kernel<<<444, 256>>>(W2, b2, n_nodes);
        gru_kernel<<<gru_grid, 512>>>(
            W1, b1, W3, b3, Wih, Whh, bih, bhh,
            (it == 5) ? out : (float*)nullptr, (it < 5) ? 1 : 0, n_nodes);
    }
}